// round 14
// baseline (speedup 1.0000x reference)
#include <cuda_runtime.h>
#include <cuda_bf16.h>
#include <math.h>
#include <stdint.h>

#define NTOK 4096            // B*T
#define DIMK 1024
#define NHEAD 16
#define DHEAD 64

// 0.125 * log2(e): folded into q so softmax is exp2(s - m)
#define QSCALE 0.18033688011112042f

// ---------------- scratch (device globals; no allocs allowed) ----------------
__device__ float g_go  [NTOK * 8];
__device__ float g_resx[NTOK * 32];
__device__ float g_resm[NTOK * 32];
__device__ float g_reso[NTOK * 32];

__device__ __nv_bfloat16 g_xn_h [NTOK * DIMK];
__device__ __nv_bfloat16 g_xn_l [NTOK * DIMK];
__device__ __nv_bfloat16 g_mn_h [NTOK * DIMK];
__device__ __nv_bfloat16 g_mn_l [NTOK * DIMK];
__device__ __nv_bfloat16 g_q_h  [NTOK * DIMK];
__device__ __nv_bfloat16 g_q_l  [NTOK * DIMK];
__device__ __nv_bfloat16 g_k_h  [NTOK * DIMK];
__device__ __nv_bfloat16 g_k_l  [NTOK * DIMK];
__device__ __nv_bfloat16 g_v_h  [NTOK * DIMK];
__device__ __nv_bfloat16 g_v_l  [NTOK * DIMK];
__device__ __nv_bfloat16 g_att_h[NTOK * DIMK];
__device__ __nv_bfloat16 g_att_l[NTOK * DIMK];
__device__ __nv_bfloat16 g_w_h  [4 * DIMK * DIMK];
__device__ __nv_bfloat16 g_w_l  [4 * DIMK * DIMK];
__device__ __nv_bfloat16 g_b16_h[4 * DIMK * 16];
__device__ __nv_bfloat16 g_b16_l[4 * DIMK * 16];
__device__ __nv_bfloat16 g_ax_h [32 * DIMK];
__device__ __nv_bfloat16 g_ax_l [32 * DIMK];
__device__ __nv_bfloat16 g_gm_h [32 * DIMK];
__device__ __nv_bfloat16 g_gm_l [32 * DIMK];
__device__ __nv_bfloat16 g_ao_h [32 * DIMK];
__device__ __nv_bfloat16 g_ao_l [32 * DIMK];
__device__ __nv_bfloat16 g_lq_h [NTOK * 16];
__device__ __nv_bfloat16 g_lq_l [NTOK * 16];
__device__ __nv_bfloat16 g_lk_h [NTOK * 16];
__device__ __nv_bfloat16 g_lk_l [NTOK * 16];
__device__ __nv_bfloat16 g_lv_h [NTOK * 16];
__device__ __nv_bfloat16 g_lv_l [NTOK * 16];
__device__ __nv_bfloat16 g_lo_h [NTOK * 16];
__device__ __nv_bfloat16 g_lo_l [NTOK * 16];

// ---------------- helpers ----------------
__device__ __forceinline__ uint32_t smem_u32(const void* p) {
    uint32_t a;
    asm("{ .reg .u64 t; cvta.to.shared.u64 t, %1; cvt.u32.u64 %0, t; }" : "=r"(a) : "l"(p));
    return a;
}

__device__ __forceinline__ void cpa16(uint32_t s, const void* g) {
    asm volatile("cp.async.cg.shared.global [%0], [%1], 16;" :: "r"(s), "l"(g));
}
#define CP_COMMIT() asm volatile("cp.async.commit_group;" ::: "memory")
#define CP_WAIT1()  asm volatile("cp.async.wait_group 1;" ::: "memory")
#define CP_WAIT0()  asm volatile("cp.async.wait_group 0;" ::: "memory")

__device__ __forceinline__ void ldsm4(uint32_t* r, uint32_t addr) {
    asm volatile("ldmatrix.sync.aligned.m8n8.x4.shared.b16 {%0,%1,%2,%3}, [%4];"
        : "=r"(r[0]), "=r"(r[1]), "=r"(r[2]), "=r"(r[3]) : "r"(addr));
}
__device__ __forceinline__ void ldsm4t(uint32_t* r, uint32_t addr) {
    asm volatile("ldmatrix.sync.aligned.m8n8.x4.trans.shared.b16 {%0,%1,%2,%3}, [%4];"
        : "=r"(r[0]), "=r"(r[1]), "=r"(r[2]), "=r"(r[3]) : "r"(addr));
}

__device__ __forceinline__ void mma16816(float* c, const uint32_t* a, const uint32_t* b) {
    asm volatile(
        "mma.sync.aligned.m16n8k16.row.col.f32.bf16.bf16.f32 "
        "{%0,%1,%2,%3}, {%4,%5,%6,%7}, {%8,%9}, {%0,%1,%2,%3};"
        : "+f"(c[0]), "+f"(c[1]), "+f"(c[2]), "+f"(c[3])
        : "r"(a[0]), "r"(a[1]), "r"(a[2]), "r"(a[3]), "r"(b[0]), "r"(b[1]));
}

__device__ __forceinline__ uint32_t swz128u(uint32_t o) { return o ^ ((o >> 3) & 0x70); }

__device__ __forceinline__ void splitf(float x, __nv_bfloat16& h, __nv_bfloat16& l) {
    h = __float2bfloat16(x);
    l = __float2bfloat16(x - __bfloat162float(h));
}
__device__ __forceinline__ uint32_t packbf(float f0, float f1) {
    uint32_t r;
    asm("cvt.rn.bf16x2.f32 %0, %1, %2;" : "=r"(r) : "f"(f1), "f"(f0));
    return r;
}
__device__ __forceinline__ void split2(float f0, float f1, uint32_t& hp, uint32_t& lp) {
    hp = packbf(f0, f1);
    float h0 = __uint_as_float(hp << 16);
    float h1 = __uint_as_float(hp & 0xffff0000u);
    lp = packbf(f0 - h0, f1 - h1);
}
__device__ __forceinline__ float ex2f(float x) {
    float r;
    asm("ex2.approx.f32 %0, %1;" : "=f"(r) : "f"(x));
    return r;
}

// ---------------- LayerNorm (x and m_tok in one launch; hi/lo bf16 outputs only) ----------------
__global__ void ln2_kernel(const float* __restrict__ in0, const float* __restrict__ g0,
                           const float* __restrict__ b0,
                           __nv_bfloat16* __restrict__ hi0, __nv_bfloat16* __restrict__ lo0,
                           const float* __restrict__ in1, const float* __restrict__ g1,
                           const float* __restrict__ b1,
                           __nv_bfloat16* __restrict__ hi1, __nv_bfloat16* __restrict__ lo1)
{
    int which = blockIdx.y;
    const float* in = which ? in1 : in0;
    const float* g  = which ? g1  : g0;
    const float* b  = which ? b1  : b0;
    __nv_bfloat16* hi = which ? hi1 : hi0;
    __nv_bfloat16* lo = which ? lo1 : lo0;
    int row = blockIdx.x;
    int tid = threadIdx.x;
    float4 a = ((const float4*)(in + (size_t)row * DIMK))[tid];
    float s = a.x + a.y + a.z + a.w;
    float q = a.x*a.x + a.y*a.y + a.z*a.z + a.w*a.w;
    #pragma unroll
    for (int o = 16; o; o >>= 1) {
        s += __shfl_xor_sync(0xffffffffu, s, o);
        q += __shfl_xor_sync(0xffffffffu, q, o);
    }
    __shared__ float ss[8], sq[8];
    __shared__ float s_mean, s_rstd;
    int warp = tid >> 5, lane = tid & 31;
    if (lane == 0) { ss[warp] = s; sq[warp] = q; }
    __syncthreads();
    if (tid == 0) {
        float ts = 0.f, tq = 0.f;
        #pragma unroll
        for (int i = 0; i < 8; i++) { ts += ss[i]; tq += sq[i]; }
        float mean = ts * (1.0f / DIMK);
        float var  = tq * (1.0f / DIMK) - mean * mean;
        s_mean = mean;
        s_rstd = rsqrtf(var + 1e-5f);
    }
    __syncthreads();
    float mean = s_mean, rstd = s_rstd;
    float4 gg = ((const float4*)g)[tid];
    float4 bb = ((const float4*)b)[tid];
    float4 r;
    r.x = (a.x - mean) * rstd * gg.x + bb.x;
    r.y = (a.y - mean) * rstd * gg.y + bb.y;
    r.z = (a.z - mean) * rstd * gg.z + bb.z;
    r.w = (a.w - mean) * rstd * gg.w + bb.w;
    uint32_t h0, l0, h1, l1;
    split2(r.x, r.y, h0, l0);
    split2(r.z, r.w, h1, l1);
    ((uint32_t*)(hi + (size_t)row * DIMK))[tid*2]   = h0;
    ((uint32_t*)(hi + (size_t)row * DIMK))[tid*2+1] = h1;
    ((uint32_t*)(lo + (size_t)row * DIMK))[tid*2]   = l0;
    ((uint32_t*)(lo + (size_t)row * DIMK))[tid*2+1] = l1;
}

// ---------------- fp32 -> hi/lo bf16 weight conversion (all 4 slots, one launch) ----------------
__global__ void cvt_w4_kernel(const float* __restrict__ w0, const float* __restrict__ w1,
                              const float* __restrict__ w2, const float* __restrict__ w3)
{
    int slot = blockIdx.y;
    const float* in = (slot == 0) ? w0 : (slot == 1) ? w1 : (slot == 2) ? w2 : w3;
    size_t i = (size_t)blockIdx.x * blockDim.x + threadIdx.x;
    float4 v = ((const float4*)in)[i];
    uint32_t hA, lA, hB, lB;
    split2(v.x, v.y, hA, lA);
    split2(v.z, v.w, hB, lB);
    size_t o = (size_t)slot * DIMK * DIMK + i * 4;
    *(uint32_t*)(g_w_h + o)     = hA;
    *(uint32_t*)(g_w_h + o + 2) = hB;
    *(uint32_t*)(g_w_l + o)     = lA;
    *(uint32_t*)(g_w_l + o + 2) = lB;
}

// ---------------- B [N,8] -> padded [N,16] hi/lo (all 4 slots) ----------------
__global__ void cvt_b4_kernel(const float* __restrict__ b0, const float* __restrict__ b1,
                              const float* __restrict__ b2, const float* __restrict__ b3)
{
    int slot = blockIdx.y;
    const float* B = (slot == 0) ? b0 : (slot == 1) ? b1 : (slot == 2) ? b2 : b3;
    int r = blockIdx.x * blockDim.x + threadIdx.x;
    if (r >= DIMK) return;
    size_t o = (size_t)slot * DIMK * 16 + (size_t)r * 16;
    __nv_bfloat16 z = __float2bfloat16(0.f);
    #pragma unroll
    for (int j = 0; j < 8; j++) {
        __nv_bfloat16 h, l;
        splitf(B[r * 8 + j], h, l);
        g_b16_h[o + j] = h; g_b16_l[o + j] = l;
        g_b16_h[o + 8 + j] = z; g_b16_l[o + 8 + j] = z;
    }
}

// ---------------- A/G/Ao vectors -> padded [32,1024] hi/lo bf16 ----------------
__global__ void cvt_vec_kernel(const float* __restrict__ Aq, const float* __restrict__ Ak,
                               const float* __restrict__ Av, const float* __restrict__ Gq,
                               const float* __restrict__ Gk, const float* __restrict__ Gv,
                               const float* __restrict__ Go, const float* __restrict__ Ao)
{
    int mat = blockIdx.y;
    int r = blockIdx.x;
    int tid = threadIdx.x;
    const float* src = 0;
    __nv_bfloat16 *dh, *dl;
    if (mat == 0) {
        dh = g_ax_h; dl = g_ax_l;
        if (r < 8) src = Aq + r * DIMK;
        else if (r < 16) src = Ak + (r - 8) * DIMK;
        else if (r < 24) src = Av + (r - 16) * DIMK;
    } else if (mat == 1) {
        dh = g_gm_h; dl = g_gm_l;
        if (r < 8) src = Gq + r * DIMK;
        else if (r < 16) src = Gk + (r - 8) * DIMK;
        else if (r < 24) src = Gv + (r - 16) * DIMK;
        else src = Go + (r - 24) * DIMK;
    } else {
        dh = g_ao_h; dl = g_ao_l;
        if (r < 8) src = Ao + r * DIMK;
    }
    float4 v = src ? ((const float4*)src)[tid] : make_float4(0.f, 0.f, 0.f, 0.f);
    uint32_t hA, lA, hB, lB;
    split2(v.x, v.y, hA, lA);
    split2(v.z, v.w, hB, lB);
    size_t o = (size_t)r * DIMK + (size_t)tid * 4;
    *(uint32_t*)(dh + o)     = hA;
    *(uint32_t*)(dh + o + 2) = hB;
    *(uint32_t*)(dl + o)     = lA;
    *(uint32_t*)(dl + o + 2) = lB;
}

// ---------------- thin split-bf16 GEMM: out[4096,32] = X[4096,1024] . V[32,1024]^T ----------------
__device__ __forceinline__
void lr_body(char* smem,
             const __nv_bfloat16* __restrict__ Xh, const __nv_bfloat16* __restrict__ Xl,
             const __nv_bfloat16* __restrict__ Vh, const __nv_bfloat16* __restrict__ Vl,
             float* __restrict__ out)
{
    const uint32_t sb = smem_u32(smem);
    const int tid = threadIdx.x;
    const int lane = tid & 31, w = tid >> 5;
    const int bm = blockIdx.x * 128;

    const int ar = tid >> 1, asg = (tid & 1) * 4;
    const int br = (tid & 63) >> 1, bsg = (tid & 1) * 4;
    auto load_stage = [&](int c, int s) {
        uint32_t sbase = sb + (uint32_t)s * 40960;
        size_t offx = (size_t)(bm + ar) * DIMK + c * 64;
        #pragma unroll
        for (int j = 0; j < 4; ++j) {
            int seg = asg + j;
            uint32_t so = sbase + swz128u((uint32_t)ar * 128 + seg * 16);
            cpa16(so,         Xh + offx + seg * 8);
            cpa16(so + 16384, Xl + offx + seg * 8);
        }
        if (tid < 64) {
            size_t offv = (size_t)br * DIMK + c * 64;
            #pragma unroll
            for (int j = 0; j < 4; ++j) {
                int seg = bsg + j;
                uint32_t so = sbase + 32768 + swz128u((uint32_t)br * 128 + seg * 16);
                cpa16(so,        Vh + offv + seg * 8);
                cpa16(so + 4096, Vl + offv + seg * 8);
            }
        }
    };

    const int rA = w * 16 + (lane & 15);
    const uint32_t aRow = (uint32_t)rA * 128;
    const uint32_t aXor = (uint32_t)((rA & 7) << 4);
    const uint32_t aK = (uint32_t)((lane >> 4) << 4);
    uint32_t bRow[2], bXor[2];
    #pragma unroll
    for (int np = 0; np < 2; ++np) {
        int rB = np * 16 + ((lane >> 4) & 1) * 8 + (lane & 7);
        bRow[np] = (uint32_t)rB * 128;
        bXor[np] = (uint32_t)((rB & 7) << 4);
    }
    const uint32_t bK = (uint32_t)(((lane >> 3) & 1) * 16);

    float acc[4][4];
    #pragma unroll
    for (int nt = 0; nt < 4; ++nt)
        #pragma unroll
        for (int i = 0; i < 4; ++i) acc[nt][i] = 0.f;

    load_stage(0, 0); CP_COMMIT();
    #pragma unroll 1
    for (int c = 0; c < 16; ++c) {
        CP_WAIT0();
        __syncthreads();
        if (c + 1 < 16) { load_stage(c + 1, (c + 1) & 1); CP_COMMIT(); }
        uint32_t sbase = sb + (uint32_t)(c & 1) * 40960;
        #pragma unroll
        for (int ks = 0; ks < 4; ++ks) {
            uint32_t kb = (uint32_t)ks * 32;
            uint32_t ah[4], al[4];
            uint32_t ad = sbase + ((aRow + kb + aK) ^ aXor);
            ldsm4(ah, ad);
            ldsm4(al, ad + 16384);
            #pragma unroll
            for (int np = 0; np < 2; ++np) {
                uint32_t bh[4], bl[4];
                uint32_t bd = sbase + 32768 + ((bRow[np] + kb + bK) ^ bXor[np]);
                ldsm4(bh, bd);
                ldsm4(bl, bd + 4096);
                #pragma unroll
                for (int hf = 0; hf < 2; ++hf) {
                    float* cc = acc[np * 2 + hf];
                    mma16816(cc, ah, &bh[hf * 2]);
                    mma16816(cc, ah, &bl[hf * 2]);
                    mma16816(cc, al, &bh[hf * 2]);
                }
            }
        }
        __syncthreads();
    }

    int m0 = bm + w * 16 + (lane >> 2);
    #pragma unroll
    for (int nt = 0; nt < 4; ++nt) {
        int n0 = nt * 8 + (lane & 3) * 2;
        *(float2*)(out + (size_t)m0 * 32 + n0)       = make_float2(acc[nt][0], acc[nt][1]);
        *(float2*)(out + (size_t)(m0 + 8) * 32 + n0) = make_float2(acc[nt][2], acc[nt][3]);
    }
}

__global__ __launch_bounds__(256, 2)
void lr_xm_kernel()
{
    extern __shared__ char smem[];
    if (blockIdx.y == 0) lr_body(smem, g_xn_h, g_xn_l, g_ax_h, g_ax_l, g_resx);
    else                 lr_body(smem, g_mn_h, g_mn_l, g_gm_h, g_gm_l, g_resm);
}
__global__ __launch_bounds__(256, 2)
void lr_o_kernel()
{
    extern __shared__ char smem[];
    lr_body(smem, g_att_h, g_att_l, g_ao_h, g_ao_l, g_reso);
}

// ---------------- combine: low-rank activations + gates ----------------
__global__ void combine_qkv_kernel()
{
    int idx = blockIdx.x * blockDim.x + threadIdx.x;
    int t = idx >> 4, j = idx & 15;
    float vq = 0.f, vk = 0.f, vv = 0.f;
    if (j < 8) {
        const float* rx = g_resx + (size_t)t * 32;
        const float* rm = g_resm + (size_t)t * 32;
        vq = 0.25f * rx[j]      * rm[j];
        vk = 0.25f * rx[8 + j]  * rm[8 + j];
        vv = 0.25f * rx[16 + j] * rm[16 + j];
        g_go[t * 8 + j] = rm[24 + j];
    }
    __nv_bfloat16 h, l;
    splitf(vq, h, l); g_lq_h[t*16 + j] = h; g_lq_l[t*16 + j] = l;
    splitf(vk, h, l); g_lk_h[t*16 + j] = h; g_lk_l[t*16 + j] = l;
    splitf(vv, h, l); g_lv_h[t*16 + j] = h; g_lv_l[t*16 + j] = l;
}
__global__ void combine_o_kernel()
{
    int idx = blockIdx.x * blockDim.x + threadIdx.x;
    int t = idx >> 4, j = idx & 15;
    float vo = 0.f;
    if (j < 8) vo = 0.25f * g_reso[(size_t)t * 32 + j] * g_go[t * 8 + j];
    __nv_bfloat16 h, l;
    splitf(vo, h, l);
    g_lo_h[t*16 + j] = h; g_lo_l[t*16 + j] = l;
}

// ---------------- HMMA split-bf16 GEMM body + folded rank-8 LoRA (champion config) ----------------
__device__ __forceinline__
void gemm_body(char* smem,
               const __nv_bfloat16* __restrict__ Xh, const __nv_bfloat16* __restrict__ Xl,
               const __nv_bfloat16* __restrict__ Wh, const __nv_bfloat16* __restrict__ Wl,
               const __nv_bfloat16* __restrict__ Lh, const __nv_bfloat16* __restrict__ Ll,
               const __nv_bfloat16* __restrict__ Bh, const __nv_bfloat16* __restrict__ Bl,
               float* __restrict__ C,
               __nv_bfloat16* __restrict__ Ch, __nv_bfloat16* __restrict__ Cl,
               float cscale)
{
    const uint32_t sb = smem_u32(smem);
    const int tid = threadIdx.x;
    const int lane = tid & 31, w = tid >> 5;
    const int wm = (w & 3) * 32, wn = (w >> 2) * 64;
    const int bm = blockIdx.y * 128, bn = blockIdx.x * 128;

    // LoRA tiles -> smem
    {
        int row = tid >> 1, cs = tid & 1;
        uint32_t so = 131072u + (uint32_t)row * 48 + cs * 16;
        size_t gl = (size_t)(bm + row) * 16 + cs * 8;
        size_t gb = (size_t)(bn + row) * 16 + cs * 8;
        *(int4*)(smem + so)          = *(const int4*)(Lh + gl);
        *(int4*)(smem + so + 6144)   = *(const int4*)(Ll + gl);
        *(int4*)(smem + so + 12288)  = *(const int4*)(Bh + gb);
        *(int4*)(smem + so + 18432)  = *(const int4*)(Bl + gb);
    }

    const int r0 = tid >> 3, seg = tid & 7;
    auto load_stage = [&](int c, int s) {
        uint32_t sbase = sb + (uint32_t)s * 65536;
        #pragma unroll
        for (int j = 0; j < 4; ++j) {
            int row = r0 + j * 32;
            size_t offx = (size_t)(bm + row) * DIMK + c * 64 + seg * 8;
            size_t offw = (size_t)(bn + row) * DIMK + c * 64 + seg * 8;
            uint32_t so = sbase + swz128u((uint32_t)row * 128 + seg * 16);
            cpa16(so,          Xh + offx);
            cpa16(so + 16384,  Xl + offx);
            cpa16(so + 32768,  Wh + offw);
            cpa16(so + 49152,  Wl + offw);
        }
    };

    uint32_t aRow[2], aXor[2];
    #pragma unroll
    for (int mt = 0; mt < 2; ++mt) {
        int rA = wm + mt * 16 + (lane & 15);
        aRow[mt] = (uint32_t)rA * 128;
        aXor[mt] = (uint32_t)((rA & 7) << 4);
    }
    const uint32_t aK = (uint32_t)((lane >> 4) << 4);
    uint32_t bRow[4], bXor[4];
    #pragma unroll
    for (int np = 0; np < 4; ++np) {
        int rB = wn + np * 16 + ((lane >> 4) & 1) * 8 + (lane & 7);
        bRow[np] = (uint32_t)rB * 128;
        bXor[np] = (uint32_t)((rB & 7) << 4);
    }
    const uint32_t bK = (uint32_t)(((lane >> 3) & 1) * 16);

    float acc[2][8][4];
    #pragma unroll
    for (int mt = 0; mt < 2; ++mt)
        #pragma unroll
        for (int nt = 0; nt < 8; ++nt)
            #pragma unroll
            for (int i = 0; i < 4; ++i) acc[mt][nt][i] = 0.f;

    auto compute = [&](int s) {
        uint32_t sbase = sb + (uint32_t)s * 65536;
        #pragma unroll
        for (int ks = 0; ks < 4; ++ks) {
            uint32_t kb = (uint32_t)ks * 32;
            uint32_t ah[2][4], al[2][4], bh[4][4], bl[4][4];
            #pragma unroll
            for (int mt = 0; mt < 2; ++mt) {
                uint32_t ad = sbase + ((aRow[mt] + kb + aK) ^ aXor[mt]);
                ldsm4(ah[mt], ad);
                ldsm4(al[mt], ad + 16384);
            }
            #pragma unroll
            for (int np = 0; np < 4; ++np) {
                uint32_t bd = sbase + 32768 + ((bRow[np] + kb + bK) ^ bXor[np]);
                ldsm4(bh[np], bd);
                ldsm4(bl[np], bd + 16384);
            }
            #pragma unroll
            for (int mt = 0; mt < 2; ++mt)
                #pragma unroll
                for (int np = 0; np < 4; ++np)
                    #pragma unroll
                    for (int hf = 0; hf < 2; ++hf) {
                        float* cc = acc[mt][np * 2 + hf];
                        mma16816(cc, ah[mt], &bh[np][hf * 2]);
                        mma16816(cc, ah[mt], &bl[np][hf * 2]);
                        mma16816(cc, al[mt], &bh[np][hf * 2]);
                    }
        }
    };

    load_stage(0, 0); CP_COMMIT();
    #pragma unroll 1
    for (int c = 0; c < 16; ++c) {
        if (c < 15) { load_stage(c + 1, (c + 1) & 1); CP_COMMIT(); CP_WAIT1(); }
        else        { CP_WAIT0(); }
        __syncthreads();
        compute(c & 1);
        __syncthreads();
    }

    // LoRA k16 step
    {
        uint32_t lb = sb + 131072u;
        uint32_t ah[2][4], al[2][4], bh[4][4], bl[4][4];
        #pragma unroll
        for (int mt = 0; mt < 2; ++mt) {
            uint32_t rA = (uint32_t)(wm + mt * 16 + (lane & 15));
            uint32_t ad = lb + rA * 48 + aK;
            ldsm4(ah[mt], ad);
            ldsm4(al[mt], ad + 6144);
        }
        #pragma unroll
        for (int np = 0; np < 4; ++np) {
            uint32_t rB = (uint32_t)(wn + np * 16 + ((lane >> 4) & 1) * 8 + (lane & 7));
            uint32_t bd = lb + 12288 + rB * 48 + bK;
            ldsm4(bh[np], bd);
            ldsm4(bl[np], bd + 6144);
        }
        #pragma unroll
        for (int mt = 0; mt < 2; ++mt)
            #pragma unroll
            for (int np = 0; np < 4; ++np)
                #pragma unroll
                for (int hf = 0; hf < 2; ++hf) {
                    float* cc = acc[mt][np * 2 + hf];
                    mma16816(cc, ah[mt], &bh[np][hf * 2]);
                    mma16816(cc, ah[mt], &bl[np][hf * 2]);
                    mma16816(cc, al[mt], &bh[np][hf * 2]);
                }
    }

    // epilogue (cscale folded into bf16 outputs; fp32 path unscaled)
    #pragma unroll
    for (int mt = 0; mt < 2; ++mt) {
        int m0 = bm + wm + mt * 16 + (lane >> 2);
        #pragma unroll
        for (int nt = 0; nt < 8; ++nt) {
            int n0 = bn + wn + nt * 8 + (lane & 3) * 2;
            float* a = acc[mt][nt];
            if (C) {
                *(float2*)(C + (size_t)m0 * DIMK + n0)       = make_float2(a[0], a[1]);
                *(float2*)(C + (size_t)(m0 + 8) * DIMK + n0) = make_float2(a[2], a[3]);
            }
            if (Ch) {
                uint32_t hp0, lp0, hp1, lp1;
                split2(a[0] * cscale, a[1] * cscale, hp0, lp0);
                split2(a[2] * cscale, a[3] * cscale, hp1, lp1);
                *(uint32_t*)(Ch + (size_t)m0 * DIMK + n0)       = hp0;
                *(uint32_t*)(Ch + (size_t)(m0 + 8) * DIMK + n0) = hp1;
                *(uint32_t*)(Cl + (size_t)m0 * DIMK + n0)       = lp0;
                *(uint32_t*)(Cl + (size_t)(m0 + 8) * DIMK + n0) = lp1;
            }
        }
    }
}

__global__ __launch_bounds__(256, 1)
void gemm_qkv_kernel()
{
    extern __shared__ char smem[];
    int z = blockIdx.z;
    const __nv_bfloat16 *Lh, *Ll;
    __nv_bfloat16 *Ch, *Cl;
    float cs;
    if (z == 0)      { Lh = g_lq_h; Ll = g_lq_l; Ch = g_q_h; Cl = g_q_l; cs = QSCALE; }
    else if (z == 1) { Lh = g_lk_h; Ll = g_lk_l; Ch = g_k_h; Cl = g_k_l; cs = 1.f; }
    else             { Lh = g_lv_h; Ll = g_lv_l; Ch = g_v_h; Cl = g_v_l; cs = 1.f; }
    gemm_body(smem, g_xn_h, g_xn_l,
              g_w_h + (size_t)z * DIMK * DIMK, g_w_l + (size_t)z * DIMK * DIMK,
              Lh, Ll, g_b16_h + (size_t)z * DIMK * 16, g_b16_l + (size_t)z * DIMK * 16,
              (float*)0, Ch, Cl, cs);
}

__global__ __launch_bounds__(256, 1)
void gemm_o_kernel(float* __restrict__ out)
{
    extern __shared__ char smem[];
    gemm_body(smem, g_att_h, g_att_l,
              g_w_h + (size_t)3 * DIMK * DIMK, g_w_l + (size_t)3 * DIMK * DIMK,
              g_lo_h, g_lo_l, g_b16_h + (size_t)3 * DIMK * 16, g_b16_l + (size_t)3 * DIMK * 16,
              out, (__nv_bfloat16*)0, (__nv_bfloat16*)0, 1.f);
}

// ---------------- HMMA split-bf16 flash attention, block-causal (frame=256) ----------------
// scale pre-folded into q; softmax in exp2 domain. RACE-FREE single-sync pipeline:
// WAIT0 -> syncthreads -> issue load(kt+1) -> compute(kt). The barrier certifies all
// warps finished reading buffer kt&1's predecessor before it is overwritten.
__global__ __launch_bounds__(256, 2)
void attn_mma_kernel()
{
    extern __shared__ char smem[];
    const uint32_t sb = smem_u32(smem);
    int qt = 15 - (int)blockIdx.x;           // big frames first
    int h  = blockIdx.y;
    int b  = blockIdx.z;
    int t0 = qt << 7;
    int ntile = ((qt >> 1) + 1) << 2;        // key tiles of 64
    int tid = threadIdx.x, lane = tid & 31, w = tid >> 5;
    size_t base = ((size_t)b * 2048) * DIMK + h * DHEAD;

    // Q load (hi+lo): 128 rows x 128B each, 2 threads/row
    {
        int lrow = tid >> 1;
        int lsegb = (tid & 1) * 4;
        size_t g = base + (size_t)(t0 + lrow) * DIMK;
        #pragma unroll
        for (int j = 0; j < 4; ++j) {
            int seg = lsegb + j;
            uint32_t so = sb + swz128u((uint32_t)lrow * 128 + seg * 16);
            cpa16(so,         g_q_h + g + seg * 8);
            cpa16(so + 16384, g_q_l + g + seg * 8);
        }
    }
    auto load_kv = [&](int kt, int st) {
        uint32_t sv = sb + 32768 + (uint32_t)st * 32768;
        int lrow = tid >> 2;
        int lsegb = (tid & 3) * 2;
        size_t g = base + (size_t)((kt << 6) + lrow) * DIMK;
        #pragma unroll
        for (int j = 0; j < 2; ++j) {
            int seg = lsegb + j;
            uint32_t so = sv + swz128u((uint32_t)lrow * 128 + seg * 16);
            cpa16(so,         g_k_h + g + seg * 8);
            cpa16(so + 8192,  g_k_l + g + seg * 8);
            cpa16(so + 16384, g_v_h + g + seg * 8);
            cpa16(so + 24576, g_v_l + g + seg * 8);
        }
    };

    const int rA = w * 16 + (lane & 15);
    const uint32_t qRow = (uint32_t)rA * 128;
    const uint32_t qXor = (uint32_t)((rA & 7) << 4);
    const uint32_t aK = (uint32_t)((lane >> 4) << 4);
    uint32_t kRow[4], kXor[4];
    #pragma unroll
    for (int np = 0; np < 4; ++np) {
        int rB = np * 16 + ((lane >> 4) & 1) * 8 + (lane & 7);
        kRow[np] = (uint32_t)rB * 128;
        kXor[np] = (uint32_t)((rB & 7) << 4);
    }
    const uint32_t bK = (uint32_t)(((lane >> 3) & 1) * 16);
    const int keyB = ((lane >> 3) & 1) * 8 + (lane & 7);
    const int dhB  = ((lane >> 4) & 1) * 8;
    const uint32_t vXor = (uint32_t)((lane & 7) << 4);

    float accO[8][4];
    #pragma unroll
    for (int nt = 0; nt < 8; ++nt)
        #pragma unroll
        for (int i = 0; i < 4; ++i) accO[nt][i] = 0.f;
    float mreg[2] = {-1e30f, -1e30f};
    float lreg[2] = {0.f, 0.f};

    load_kv(0, 0); CP_COMMIT();

    #pragma unroll 1
    for (int kt = 0; kt < ntile; ++kt) {
        CP_WAIT0();
        __syncthreads();                     // all warps done with buffer kt&1's previous contents
        if (kt + 1 < ntile) { load_kv(kt + 1, (kt + 1) & 1); CP_COMMIT(); }
        uint32_t kb = sb + 32768 + (uint32_t)(kt & 1) * 32768;
        uint32_t vb = kb + 16384;

        // S = QK^T (3-term split); K frags per-np to limit liveness
        float s[8][4];
        #pragma unroll
        for (int nt = 0; nt < 8; ++nt)
            #pragma unroll
            for (int i = 0; i < 4; ++i) s[nt][i] = 0.f;
        #pragma unroll
        for (int ks = 0; ks < 4; ++ks) {
            uint32_t kbyte = (uint32_t)ks * 32;
            uint32_t ah[4], al[4];
            uint32_t ad = sb + ((qRow + kbyte + aK) ^ qXor);
            ldsm4(ah, ad);
            ldsm4(al, ad + 16384);
            #pragma unroll
            for (int np = 0; np < 4; ++np) {
                uint32_t bh[4], bl[4];
                uint32_t bd = kb + ((kRow[np] + kbyte + bK) ^ kXor[np]);
                ldsm4(bh, bd);
                ldsm4(bl, bd + 8192);
                #pragma unroll
                for (int hf = 0; hf < 2; ++hf) {
                    float* cc = s[np * 2 + hf];
                    mma16816(cc, ah, &bh[hf * 2]);
                    mma16816(cc, ah, &bl[hf * 2]);
                    mma16816(cc, al, &bh[hf * 2]);
                }
            }
        }

        // online softmax in exp2 domain (logits pre-scaled)
        #pragma unroll
        for (int i = 0; i < 2; ++i) {
            float mx = -1e30f;
            #pragma unroll
            for (int nt = 0; nt < 8; ++nt)
                mx = fmaxf(mx, fmaxf(s[nt][2*i], s[nt][2*i+1]));
            mx = fmaxf(mx, __shfl_xor_sync(0xffffffffu, mx, 1));
            mx = fmaxf(mx, __shfl_xor_sync(0xffffffffu, mx, 2));
            float mnew = fmaxf(mreg[i], mx);
            float corr = ex2f(mreg[i] - mnew);
            mreg[i] = mnew;
            float rs = 0.f;
            #pragma unroll
            for (int nt = 0; nt < 8; ++nt) {
                float p0 = ex2f(s[nt][2*i]   - mnew);
                float p1 = ex2f(s[nt][2*i+1] - mnew);
                s[nt][2*i] = p0; s[nt][2*i+1] = p1;
                rs += p0 + p1;
            }
            rs += __shfl_xor_sync(0xffffffffu, rs, 1);
            rs += __shfl_xor_sync(0xffffffffu, rs, 2);
            lreg[i] = lreg[i] * corr + rs;
            #pragma unroll
            for (int nt = 0; nt < 8; ++nt) {
                accO[nt][2*i]   *= corr;
                accO[nt][2*i+1] *= corr;
            }
        }

        // O += P V (3-term split); V frags per-np to limit liveness
        #pragma unroll
        for (int kp = 0; kp < 4; ++kp) {
            uint32_t paH[4], paL[4];
            #pragma unroll
            for (int q4 = 0; q4 < 4; ++q4) {
                int nt = kp * 2 + (q4 >> 1);
                int e0 = (q4 & 1) * 2;
                split2(s[nt][e0], s[nt][e0 + 1], paH[q4], paL[q4]);
            }
            uint32_t vrow = (uint32_t)(kp * 16 + keyB) * 128;
            #pragma unroll
            for (int np = 0; np < 4; ++np) {
                uint32_t vh4[4], vl4[4];
                uint32_t bd = vb + ((vrow + (uint32_t)(np * 16 + dhB) * 2) ^ vXor);
                ldsm4t(vh4, bd);
                ldsm4t(vl4, bd + 8192);
                #pragma unroll
                for (int hf = 0; hf < 2; ++hf) {
                    float* cc = accO[np * 2 + hf];
                    mma16816(cc, paH, &vh4[hf * 2]);
                    mma16816(cc, paH, &vl4[hf * 2]);
                    mma16816(cc, paL, &vh4[hf * 2]);
                }
            }
        }
    }

    // epilogue: hi/lo bf16 att only
    #pragma unroll
    for (int i = 0; i < 2; ++i) {
        float inv = 1.0f / lreg[i];
        int row = t0 + w * 16 + (lane >> 2) + i * 8;
        size_t rb = base + (size_t)row * DIMK;
        #pragma unroll
        for (int nt = 0; nt < 8; ++nt) {
            int col = nt * 8 + (lane & 3) * 2;
            float f0 = accO[nt][2*i] * inv, f1 = accO[nt][2*i+1] * inv;
            uint32_t hp, lp;
            split2(f0, f1, hp, lp);
            *(uint32_t*)(g_att_h + rb + col) = hp;
            *(uint32_t*)(g_att_l + rb + col) = lp;
        }
    }
}

// ---------------- launch ----------------
extern "C" void kernel_launch(void* const* d_in, const int* in_sizes, int n_in,
                              void* d_out, int out_size)
{
    (void)in_sizes; (void)n_in; (void)out_size;
    const float* x      = (const float*)d_in[0];
    const float* m_tok  = (const float*)d_in[1];
    const float* norm_g = (const float*)d_in[2];
    const float* norm_b = (const float*)d_in[3];
    const float* mnorm_g= (const float*)d_in[4];
    const float* mnorm_b= (const float*)d_in[5];
    const float* Wq = (const float*)d_in[6];
    const float* Aq = (const float*)d_in[7];
    const float* Bq = (const float*)d_in[8];
    const float* Gq = (const float*)d_in[9];
    const float* Wk = (const float*)d_in[10];
    const float* Ak = (const float*)d_in[11];
    const float* Bk = (const float*)d_in[12];
    const float* Gk = (const float*)d_in[13];
    const float* Wv = (const float*)d_in[14];
    const float* Av = (const float*)d_in[15];
    const float* Bv = (const float*)d_in[16];
    const float* Gv = (const float*)d_in[17];
    const float* Wo = (const float*)d_in[18];
    const float* Ao = (const float*)d_in[19];
    const float* Bo = (const float*)d_in[20];
    const float* Go = (const float*)d_in[21];
    float* out = (float*)d_out;

    __nv_bfloat16 *p_xnh, *p_xnl, *p_mnh, *p_mnl;
    cudaGetSymbolAddress((void**)&p_xnh, g_xn_h);
    cudaGetSymbolAddress((void**)&p_xnl, g_xn_l);
    cudaGetSymbolAddress((void**)&p_mnh, g_mn_h);
    cudaGetSymbolAddress((void**)&p_mnl, g_mn_l);

    const int GSMEM = 2 * 65536 + 4 * 6144;        // 152 KB
    const int ASMEM = 32768 + 2 * 32768;           // 96 KB
    const int RSMEM = 2 * 40960;                   // 80 KB
    cudaFuncSetAttribute(gemm_qkv_kernel, cudaFuncAttributeMaxDynamicSharedMemorySize, GSMEM);
    cudaFuncSetAttribute(gemm_o_kernel,   cudaFuncAttributeMaxDynamicSharedMemorySize, GSMEM);
    cudaFuncSetAttribute(attn_mma_kernel, cudaFuncAttributeMaxDynamicSharedMemorySize, ASMEM);
    cudaFuncSetAttribute(lr_xm_kernel,    cudaFuncAttributeMaxDynamicSharedMemorySize, RSMEM);
    cudaFuncSetAttribute(lr_o_kernel,     cudaFuncAttributeMaxDynamicSharedMemorySize, RSMEM);

    cvt_w4_kernel<<<dim3(1024, 4), 256>>>(Wq, Wk, Wv, Wo);
    cvt_b4_kernel<<<dim3(4, 4), 256>>>(Bq, Bk, Bv, Bo);
    cvt_vec_kernel<<<dim3(32, 3), 256>>>(Aq, Ak, Av, Gq, Gk, Gv, Go, Ao);

    ln2_kernel<<<dim3(NTOK, 2), 256>>>(x, norm_g, norm_b, p_xnh, p_xnl,
                                       m_tok, mnorm_g, mnorm_b, p_mnh, p_mnl);

    lr_xm_kernel<<<dim3(32, 2), 256, RSMEM>>>();
    combine_qkv_kernel<<<256, 256>>>();

    gemm_qkv_kernel<<<dim3(8, 32, 3), 256, GSMEM>>>();

    attn_mma_kernel<<<dim3(16, 16, 2), 256, ASMEM>>>();

    lr_o_kernel<<<32, 256, RSMEM>>>();
    combine_o_kernel<<<256, 256>>>();
    gemm_o_kernel<<<dim3(8, 32), 256, GSMEM>>>(out);
}

// round 15
// speedup vs baseline: 1.0454x; 1.0454x over previous
#include <cuda_runtime.h>
#include <cuda_bf16.h>
#include <math.h>
#include <stdint.h>

#define NTOK 4096            // B*T
#define DIMK 1024
#define NHEAD 16
#define DHEAD 64

// 0.125 * log2(e): folded into q so softmax is exp2(s - m)
#define QSCALE 0.18033688011112042f

// ---------------- scratch (device globals; no allocs allowed) ----------------
__device__ float g_go  [NTOK * 8];
__device__ float g_resx[NTOK * 32];
__device__ float g_resm[NTOK * 32];
__device__ float g_reso[NTOK * 32];

__device__ __nv_bfloat16 g_xn_h [NTOK * DIMK];
__device__ __nv_bfloat16 g_xn_l [NTOK * DIMK];
__device__ __nv_bfloat16 g_mn_h [NTOK * DIMK];
__device__ __nv_bfloat16 g_mn_l [NTOK * DIMK];
__device__ __nv_bfloat16 g_q_h  [NTOK * DIMK];
__device__ __nv_bfloat16 g_q_l  [NTOK * DIMK];
__device__ __nv_bfloat16 g_k_h  [NTOK * DIMK];
__device__ __nv_bfloat16 g_k_l  [NTOK * DIMK];
__device__ __nv_bfloat16 g_v_h  [NTOK * DIMK];
__device__ __nv_bfloat16 g_v_l  [NTOK * DIMK];
__device__ __nv_bfloat16 g_att_h[NTOK * DIMK];
__device__ __nv_bfloat16 g_att_l[NTOK * DIMK];
__device__ __nv_bfloat16 g_w_h  [4 * DIMK * DIMK];
__device__ __nv_bfloat16 g_w_l  [4 * DIMK * DIMK];
__device__ __nv_bfloat16 g_b16_h[4 * DIMK * 16];
__device__ __nv_bfloat16 g_b16_l[4 * DIMK * 16];
__device__ __nv_bfloat16 g_ax_h [32 * DIMK];
__device__ __nv_bfloat16 g_ax_l [32 * DIMK];
__device__ __nv_bfloat16 g_gm_h [32 * DIMK];
__device__ __nv_bfloat16 g_gm_l [32 * DIMK];
__device__ __nv_bfloat16 g_ao_h [32 * DIMK];
__device__ __nv_bfloat16 g_ao_l [32 * DIMK];
__device__ __nv_bfloat16 g_lq_h [NTOK * 16];
__device__ __nv_bfloat16 g_lq_l [NTOK * 16];
__device__ __nv_bfloat16 g_lk_h [NTOK * 16];
__device__ __nv_bfloat16 g_lk_l [NTOK * 16];
__device__ __nv_bfloat16 g_lv_h [NTOK * 16];
__device__ __nv_bfloat16 g_lv_l [NTOK * 16];
__device__ __nv_bfloat16 g_lo_h [NTOK * 16];
__device__ __nv_bfloat16 g_lo_l [NTOK * 16];

// ---------------- helpers ----------------
__device__ __forceinline__ uint32_t smem_u32(const void* p) {
    uint32_t a;
    asm("{ .reg .u64 t; cvta.to.shared.u64 t, %1; cvt.u32.u64 %0, t; }" : "=r"(a) : "l"(p));
    return a;
}

__device__ __forceinline__ void cpa16(uint32_t s, const void* g) {
    asm volatile("cp.async.cg.shared.global [%0], [%1], 16;" :: "r"(s), "l"(g));
}
#define CP_COMMIT() asm volatile("cp.async.commit_group;" ::: "memory")
#define CP_WAIT1()  asm volatile("cp.async.wait_group 1;" ::: "memory")
#define CP_WAIT0()  asm volatile("cp.async.wait_group 0;" ::: "memory")

__device__ __forceinline__ void ldsm4(uint32_t* r, uint32_t addr) {
    asm volatile("ldmatrix.sync.aligned.m8n8.x4.shared.b16 {%0,%1,%2,%3}, [%4];"
        : "=r"(r[0]), "=r"(r[1]), "=r"(r[2]), "=r"(r[3]) : "r"(addr));
}
__device__ __forceinline__ void ldsm4t(uint32_t* r, uint32_t addr) {
    asm volatile("ldmatrix.sync.aligned.m8n8.x4.trans.shared.b16 {%0,%1,%2,%3}, [%4];"
        : "=r"(r[0]), "=r"(r[1]), "=r"(r[2]), "=r"(r[3]) : "r"(addr));
}

__device__ __forceinline__ void mma16816(float* c, const uint32_t* a, const uint32_t* b) {
    asm volatile(
        "mma.sync.aligned.m16n8k16.row.col.f32.bf16.bf16.f32 "
        "{%0,%1,%2,%3}, {%4,%5,%6,%7}, {%8,%9}, {%0,%1,%2,%3};"
        : "+f"(c[0]), "+f"(c[1]), "+f"(c[2]), "+f"(c[3])
        : "r"(a[0]), "r"(a[1]), "r"(a[2]), "r"(a[3]), "r"(b[0]), "r"(b[1]));
}

__device__ __forceinline__ uint32_t swz128u(uint32_t o) { return o ^ ((o >> 3) & 0x70); }

__device__ __forceinline__ void splitf(float x, __nv_bfloat16& h, __nv_bfloat16& l) {
    h = __float2bfloat16(x);
    l = __float2bfloat16(x - __bfloat162float(h));
}
__device__ __forceinline__ uint32_t packbf(float f0, float f1) {
    uint32_t r;
    asm("cvt.rn.bf16x2.f32 %0, %1, %2;" : "=r"(r) : "f"(f1), "f"(f0));
    return r;
}
__device__ __forceinline__ void split2(float f0, float f1, uint32_t& hp, uint32_t& lp) {
    hp = packbf(f0, f1);
    float h0 = __uint_as_float(hp << 16);
    float h1 = __uint_as_float(hp & 0xffff0000u);
    lp = packbf(f0 - h0, f1 - h1);
}
__device__ __forceinline__ float ex2f(float x) {
    float r;
    asm("ex2.approx.f32 %0, %1;" : "=f"(r) : "f"(x));
    return r;
}

// ---------------- LayerNorm (x and m_tok in one launch; hi/lo bf16 outputs only) ----------------
__global__ void ln2_kernel(const float* __restrict__ in0, const float* __restrict__ g0,
                           const float* __restrict__ b0,
                           __nv_bfloat16* __restrict__ hi0, __nv_bfloat16* __restrict__ lo0,
                           const float* __restrict__ in1, const float* __restrict__ g1,
                           const float* __restrict__ b1,
                           __nv_bfloat16* __restrict__ hi1, __nv_bfloat16* __restrict__ lo1)
{
    int which = blockIdx.y;
    const float* in = which ? in1 : in0;
    const float* g  = which ? g1  : g0;
    const float* b  = which ? b1  : b0;
    __nv_bfloat16* hi = which ? hi1 : hi0;
    __nv_bfloat16* lo = which ? lo1 : lo0;
    int row = blockIdx.x;
    int tid = threadIdx.x;
    float4 a = ((const float4*)(in + (size_t)row * DIMK))[tid];
    float s = a.x + a.y + a.z + a.w;
    float q = a.x*a.x + a.y*a.y + a.z*a.z + a.w*a.w;
    #pragma unroll
    for (int o = 16; o; o >>= 1) {
        s += __shfl_xor_sync(0xffffffffu, s, o);
        q += __shfl_xor_sync(0xffffffffu, q, o);
    }
    __shared__ float ss[8], sq[8];
    __shared__ float s_mean, s_rstd;
    int warp = tid >> 5, lane = tid & 31;
    if (lane == 0) { ss[warp] = s; sq[warp] = q; }
    __syncthreads();
    if (tid == 0) {
        float ts = 0.f, tq = 0.f;
        #pragma unroll
        for (int i = 0; i < 8; i++) { ts += ss[i]; tq += sq[i]; }
        float mean = ts * (1.0f / DIMK);
        float var  = tq * (1.0f / DIMK) - mean * mean;
        s_mean = mean;
        s_rstd = rsqrtf(var + 1e-5f);
    }
    __syncthreads();
    float mean = s_mean, rstd = s_rstd;
    float4 gg = ((const float4*)g)[tid];
    float4 bb = ((const float4*)b)[tid];
    float4 r;
    r.x = (a.x - mean) * rstd * gg.x + bb.x;
    r.y = (a.y - mean) * rstd * gg.y + bb.y;
    r.z = (a.z - mean) * rstd * gg.z + bb.z;
    r.w = (a.w - mean) * rstd * gg.w + bb.w;
    uint32_t h0, l0, h1, l1;
    split2(r.x, r.y, h0, l0);
    split2(r.z, r.w, h1, l1);
    ((uint32_t*)(hi + (size_t)row * DIMK))[tid*2]   = h0;
    ((uint32_t*)(hi + (size_t)row * DIMK))[tid*2+1] = h1;
    ((uint32_t*)(lo + (size_t)row * DIMK))[tid*2]   = l0;
    ((uint32_t*)(lo + (size_t)row * DIMK))[tid*2+1] = l1;
}

// ---------------- fp32 -> hi/lo bf16 weight conversion (all 4 slots, one launch) ----------------
__global__ void cvt_w4_kernel(const float* __restrict__ w0, const float* __restrict__ w1,
                              const float* __restrict__ w2, const float* __restrict__ w3)
{
    int slot = blockIdx.y;
    const float* in = (slot == 0) ? w0 : (slot == 1) ? w1 : (slot == 2) ? w2 : w3;
    size_t i = (size_t)blockIdx.x * blockDim.x + threadIdx.x;
    float4 v = ((const float4*)in)[i];
    uint32_t hA, lA, hB, lB;
    split2(v.x, v.y, hA, lA);
    split2(v.z, v.w, hB, lB);
    size_t o = (size_t)slot * DIMK * DIMK + i * 4;
    *(uint32_t*)(g_w_h + o)     = hA;
    *(uint32_t*)(g_w_h + o + 2) = hB;
    *(uint32_t*)(g_w_l + o)     = lA;
    *(uint32_t*)(g_w_l + o + 2) = lB;
}

// ---------------- B [N,8] -> padded [N,16] hi/lo (all 4 slots) ----------------
__global__ void cvt_b4_kernel(const float* __restrict__ b0, const float* __restrict__ b1,
                              const float* __restrict__ b2, const float* __restrict__ b3)
{
    int slot = blockIdx.y;
    const float* B = (slot == 0) ? b0 : (slot == 1) ? b1 : (slot == 2) ? b2 : b3;
    int r = blockIdx.x * blockDim.x + threadIdx.x;
    if (r >= DIMK) return;
    size_t o = (size_t)slot * DIMK * 16 + (size_t)r * 16;
    __nv_bfloat16 z = __float2bfloat16(0.f);
    #pragma unroll
    for (int j = 0; j < 8; j++) {
        __nv_bfloat16 h, l;
        splitf(B[r * 8 + j], h, l);
        g_b16_h[o + j] = h; g_b16_l[o + j] = l;
        g_b16_h[o + 8 + j] = z; g_b16_l[o + 8 + j] = z;
    }
}

// ---------------- A/G/Ao vectors -> padded [32,1024] hi/lo bf16 ----------------
__global__ void cvt_vec_kernel(const float* __restrict__ Aq, const float* __restrict__ Ak,
                               const float* __restrict__ Av, const float* __restrict__ Gq,
                               const float* __restrict__ Gk, const float* __restrict__ Gv,
                               const float* __restrict__ Go, const float* __restrict__ Ao)
{
    int mat = blockIdx.y;
    int r = blockIdx.x;
    int tid = threadIdx.x;
    const float* src = 0;
    __nv_bfloat16 *dh, *dl;
    if (mat == 0) {
        dh = g_ax_h; dl = g_ax_l;
        if (r < 8) src = Aq + r * DIMK;
        else if (r < 16) src = Ak + (r - 8) * DIMK;
        else if (r < 24) src = Av + (r - 16) * DIMK;
    } else if (mat == 1) {
        dh = g_gm_h; dl = g_gm_l;
        if (r < 8) src = Gq + r * DIMK;
        else if (r < 16) src = Gk + (r - 8) * DIMK;
        else if (r < 24) src = Gv + (r - 16) * DIMK;
        else src = Go + (r - 24) * DIMK;
    } else {
        dh = g_ao_h; dl = g_ao_l;
        if (r < 8) src = Ao + r * DIMK;
    }
    float4 v = src ? ((const float4*)src)[tid] : make_float4(0.f, 0.f, 0.f, 0.f);
    uint32_t hA, lA, hB, lB;
    split2(v.x, v.y, hA, lA);
    split2(v.z, v.w, hB, lB);
    size_t o = (size_t)r * DIMK + (size_t)tid * 4;
    *(uint32_t*)(dh + o)     = hA;
    *(uint32_t*)(dh + o + 2) = hB;
    *(uint32_t*)(dl + o)     = lA;
    *(uint32_t*)(dl + o + 2) = lB;
}

// ---------------- thin split-bf16 GEMM: out[4096,32] = X[4096,1024] . V[32,1024]^T ----------------
__device__ __forceinline__
void lr_body(char* smem,
             const __nv_bfloat16* __restrict__ Xh, const __nv_bfloat16* __restrict__ Xl,
             const __nv_bfloat16* __restrict__ Vh, const __nv_bfloat16* __restrict__ Vl,
             float* __restrict__ out)
{
    const uint32_t sb = smem_u32(smem);
    const int tid = threadIdx.x;
    const int lane = tid & 31, w = tid >> 5;
    const int bm = blockIdx.x * 128;

    const int ar = tid >> 1, asg = (tid & 1) * 4;
    const int br = (tid & 63) >> 1, bsg = (tid & 1) * 4;
    auto load_stage = [&](int c, int s) {
        uint32_t sbase = sb + (uint32_t)s * 40960;
        size_t offx = (size_t)(bm + ar) * DIMK + c * 64;
        #pragma unroll
        for (int j = 0; j < 4; ++j) {
            int seg = asg + j;
            uint32_t so = sbase + swz128u((uint32_t)ar * 128 + seg * 16);
            cpa16(so,         Xh + offx + seg * 8);
            cpa16(so + 16384, Xl + offx + seg * 8);
        }
        if (tid < 64) {
            size_t offv = (size_t)br * DIMK + c * 64;
            #pragma unroll
            for (int j = 0; j < 4; ++j) {
                int seg = bsg + j;
                uint32_t so = sbase + 32768 + swz128u((uint32_t)br * 128 + seg * 16);
                cpa16(so,        Vh + offv + seg * 8);
                cpa16(so + 4096, Vl + offv + seg * 8);
            }
        }
    };

    const int rA = w * 16 + (lane & 15);
    const uint32_t aRow = (uint32_t)rA * 128;
    const uint32_t aXor = (uint32_t)((rA & 7) << 4);
    const uint32_t aK = (uint32_t)((lane >> 4) << 4);
    uint32_t bRow[2], bXor[2];
    #pragma unroll
    for (int np = 0; np < 2; ++np) {
        int rB = np * 16 + ((lane >> 4) & 1) * 8 + (lane & 7);
        bRow[np] = (uint32_t)rB * 128;
        bXor[np] = (uint32_t)((rB & 7) << 4);
    }
    const uint32_t bK = (uint32_t)(((lane >> 3) & 1) * 16);

    float acc[4][4];
    #pragma unroll
    for (int nt = 0; nt < 4; ++nt)
        #pragma unroll
        for (int i = 0; i < 4; ++i) acc[nt][i] = 0.f;

    load_stage(0, 0); CP_COMMIT();
    #pragma unroll 1
    for (int c = 0; c < 16; ++c) {
        CP_WAIT0();
        __syncthreads();
        if (c + 1 < 16) { load_stage(c + 1, (c + 1) & 1); CP_COMMIT(); }
        uint32_t sbase = sb + (uint32_t)(c & 1) * 40960;
        #pragma unroll
        for (int ks = 0; ks < 4; ++ks) {
            uint32_t kb = (uint32_t)ks * 32;
            uint32_t ah[4], al[4];
            uint32_t ad = sbase + ((aRow + kb + aK) ^ aXor);
            ldsm4(ah, ad);
            ldsm4(al, ad + 16384);
            #pragma unroll
            for (int np = 0; np < 2; ++np) {
                uint32_t bh[4], bl[4];
                uint32_t bd = sbase + 32768 + ((bRow[np] + kb + bK) ^ bXor[np]);
                ldsm4(bh, bd);
                ldsm4(bl, bd + 4096);
                #pragma unroll
                for (int hf = 0; hf < 2; ++hf) {
                    float* cc = acc[np * 2 + hf];
                    mma16816(cc, ah, &bh[hf * 2]);
                    mma16816(cc, ah, &bl[hf * 2]);
                    mma16816(cc, al, &bh[hf * 2]);
                }
            }
        }
        __syncthreads();
    }

    int m0 = bm + w * 16 + (lane >> 2);
    #pragma unroll
    for (int nt = 0; nt < 4; ++nt) {
        int n0 = nt * 8 + (lane & 3) * 2;
        *(float2*)(out + (size_t)m0 * 32 + n0)       = make_float2(acc[nt][0], acc[nt][1]);
        *(float2*)(out + (size_t)(m0 + 8) * 32 + n0) = make_float2(acc[nt][2], acc[nt][3]);
    }
}

__global__ __launch_bounds__(256, 2)
void lr_xm_kernel()
{
    extern __shared__ char smem[];
    if (blockIdx.y == 0) lr_body(smem, g_xn_h, g_xn_l, g_ax_h, g_ax_l, g_resx);
    else                 lr_body(smem, g_mn_h, g_mn_l, g_gm_h, g_gm_l, g_resm);
}
__global__ __launch_bounds__(256, 2)
void lr_o_kernel()
{
    extern __shared__ char smem[];
    lr_body(smem, g_att_h, g_att_l, g_ao_h, g_ao_l, g_reso);
}

// ---------------- combine: low-rank activations + gates ----------------
__global__ void combine_qkv_kernel()
{
    int idx = blockIdx.x * blockDim.x + threadIdx.x;
    int t = idx >> 4, j = idx & 15;
    float vq = 0.f, vk = 0.f, vv = 0.f;
    if (j < 8) {
        const float* rx = g_resx + (size_t)t * 32;
        const float* rm = g_resm + (size_t)t * 32;
        vq = 0.25f * rx[j]      * rm[j];
        vk = 0.25f * rx[8 + j]  * rm[8 + j];
        vv = 0.25f * rx[16 + j] * rm[16 + j];
        g_go[t * 8 + j] = rm[24 + j];
    }
    __nv_bfloat16 h, l;
    splitf(vq, h, l); g_lq_h[t*16 + j] = h; g_lq_l[t*16 + j] = l;
    splitf(vk, h, l); g_lk_h[t*16 + j] = h; g_lk_l[t*16 + j] = l;
    splitf(vv, h, l); g_lv_h[t*16 + j] = h; g_lv_l[t*16 + j] = l;
}
__global__ void combine_o_kernel()
{
    int idx = blockIdx.x * blockDim.x + threadIdx.x;
    int t = idx >> 4, j = idx & 15;
    float vo = 0.f;
    if (j < 8) vo = 0.25f * g_reso[(size_t)t * 32 + j] * g_go[t * 8 + j];
    __nv_bfloat16 h, l;
    splitf(vo, h, l);
    g_lo_h[t*16 + j] = h; g_lo_l[t*16 + j] = l;
}

// ---------------- HMMA split-bf16 GEMM body + folded rank-8 LoRA (champion config) ----------------
__device__ __forceinline__
void gemm_body(char* smem,
               const __nv_bfloat16* __restrict__ Xh, const __nv_bfloat16* __restrict__ Xl,
               const __nv_bfloat16* __restrict__ Wh, const __nv_bfloat16* __restrict__ Wl,
               const __nv_bfloat16* __restrict__ Lh, const __nv_bfloat16* __restrict__ Ll,
               const __nv_bfloat16* __restrict__ Bh, const __nv_bfloat16* __restrict__ Bl,
               float* __restrict__ C,
               __nv_bfloat16* __restrict__ Ch, __nv_bfloat16* __restrict__ Cl,
               float cscale)
{
    const uint32_t sb = smem_u32(smem);
    const int tid = threadIdx.x;
    const int lane = tid & 31, w = tid >> 5;
    const int wm = (w & 3) * 32, wn = (w >> 2) * 64;
    const int bm = blockIdx.y * 128, bn = blockIdx.x * 128;

    // LoRA tiles -> smem
    {
        int row = tid >> 1, cs = tid & 1;
        uint32_t so = 131072u + (uint32_t)row * 48 + cs * 16;
        size_t gl = (size_t)(bm + row) * 16 + cs * 8;
        size_t gb = (size_t)(bn + row) * 16 + cs * 8;
        *(int4*)(smem + so)          = *(const int4*)(Lh + gl);
        *(int4*)(smem + so + 6144)   = *(const int4*)(Ll + gl);
        *(int4*)(smem + so + 12288)  = *(const int4*)(Bh + gb);
        *(int4*)(smem + so + 18432)  = *(const int4*)(Bl + gb);
    }

    const int r0 = tid >> 3, seg = tid & 7;
    auto load_stage = [&](int c, int s) {
        uint32_t sbase = sb + (uint32_t)s * 65536;
        #pragma unroll
        for (int j = 0; j < 4; ++j) {
            int row = r0 + j * 32;
            size_t offx = (size_t)(bm + row) * DIMK + c * 64 + seg * 8;
            size_t offw = (size_t)(bn + row) * DIMK + c * 64 + seg * 8;
            uint32_t so = sbase + swz128u((uint32_t)row * 128 + seg * 16);
            cpa16(so,          Xh + offx);
            cpa16(so + 16384,  Xl + offx);
            cpa16(so + 32768,  Wh + offw);
            cpa16(so + 49152,  Wl + offw);
        }
    };

    uint32_t aRow[2], aXor[2];
    #pragma unroll
    for (int mt = 0; mt < 2; ++mt) {
        int rA = wm + mt * 16 + (lane & 15);
        aRow[mt] = (uint32_t)rA * 128;
        aXor[mt] = (uint32_t)((rA & 7) << 4);
    }
    const uint32_t aK = (uint32_t)((lane >> 4) << 4);
    uint32_t bRow[4], bXor[4];
    #pragma unroll
    for (int np = 0; np < 4; ++np) {
        int rB = wn + np * 16 + ((lane >> 4) & 1) * 8 + (lane & 7);
        bRow[np] = (uint32_t)rB * 128;
        bXor[np] = (uint32_t)((rB & 7) << 4);
    }
    const uint32_t bK = (uint32_t)(((lane >> 3) & 1) * 16);

    float acc[2][8][4];
    #pragma unroll
    for (int mt = 0; mt < 2; ++mt)
        #pragma unroll
        for (int nt = 0; nt < 8; ++nt)
            #pragma unroll
            for (int i = 0; i < 4; ++i) acc[mt][nt][i] = 0.f;

    auto compute = [&](int s) {
        uint32_t sbase = sb + (uint32_t)s * 65536;
        #pragma unroll
        for (int ks = 0; ks < 4; ++ks) {
            uint32_t kb = (uint32_t)ks * 32;
            uint32_t ah[2][4], al[2][4], bh[4][4], bl[4][4];
            #pragma unroll
            for (int mt = 0; mt < 2; ++mt) {
                uint32_t ad = sbase + ((aRow[mt] + kb + aK) ^ aXor[mt]);
                ldsm4(ah[mt], ad);
                ldsm4(al[mt], ad + 16384);
            }
            #pragma unroll
            for (int np = 0; np < 4; ++np) {
                uint32_t bd = sbase + 32768 + ((bRow[np] + kb + bK) ^ bXor[np]);
                ldsm4(bh[np], bd);
                ldsm4(bl[np], bd + 16384);
            }
            #pragma unroll
            for (int mt = 0; mt < 2; ++mt)
                #pragma unroll
                for (int np = 0; np < 4; ++np)
                    #pragma unroll
                    for (int hf = 0; hf < 2; ++hf) {
                        float* cc = acc[mt][np * 2 + hf];
                        mma16816(cc, ah[mt], &bh[np][hf * 2]);
                        mma16816(cc, ah[mt], &bl[np][hf * 2]);
                        mma16816(cc, al[mt], &bh[np][hf * 2]);
                    }
        }
    };

    load_stage(0, 0); CP_COMMIT();
    #pragma unroll 1
    for (int c = 0; c < 16; ++c) {
        if (c < 15) { load_stage(c + 1, (c + 1) & 1); CP_COMMIT(); CP_WAIT1(); }
        else        { CP_WAIT0(); }
        __syncthreads();
        compute(c & 1);
        __syncthreads();
    }

    // LoRA k16 step
    {
        uint32_t lb = sb + 131072u;
        uint32_t ah[2][4], al[2][4], bh[4][4], bl[4][4];
        #pragma unroll
        for (int mt = 0; mt < 2; ++mt) {
            uint32_t rA = (uint32_t)(wm + mt * 16 + (lane & 15));
            uint32_t ad = lb + rA * 48 + aK;
            ldsm4(ah[mt], ad);
            ldsm4(al[mt], ad + 6144);
        }
        #pragma unroll
        for (int np = 0; np < 4; ++np) {
            uint32_t rB = (uint32_t)(wn + np * 16 + ((lane >> 4) & 1) * 8 + (lane & 7));
            uint32_t bd = lb + 12288 + rB * 48 + bK;
            ldsm4(bh[np], bd);
            ldsm4(bl[np], bd + 6144);
        }
        #pragma unroll
        for (int mt = 0; mt < 2; ++mt)
            #pragma unroll
            for (int np = 0; np < 4; ++np)
                #pragma unroll
                for (int hf = 0; hf < 2; ++hf) {
                    float* cc = acc[mt][np * 2 + hf];
                    mma16816(cc, ah[mt], &bh[np][hf * 2]);
                    mma16816(cc, ah[mt], &bl[np][hf * 2]);
                    mma16816(cc, al[mt], &bh[np][hf * 2]);
                }
    }

    // epilogue (cscale folded into bf16 outputs; fp32 path unscaled)
    #pragma unroll
    for (int mt = 0; mt < 2; ++mt) {
        int m0 = bm + wm + mt * 16 + (lane >> 2);
        #pragma unroll
        for (int nt = 0; nt < 8; ++nt) {
            int n0 = bn + wn + nt * 8 + (lane & 3) * 2;
            float* a = acc[mt][nt];
            if (C) {
                *(float2*)(C + (size_t)m0 * DIMK + n0)       = make_float2(a[0], a[1]);
                *(float2*)(C + (size_t)(m0 + 8) * DIMK + n0) = make_float2(a[2], a[3]);
            }
            if (Ch) {
                uint32_t hp0, lp0, hp1, lp1;
                split2(a[0] * cscale, a[1] * cscale, hp0, lp0);
                split2(a[2] * cscale, a[3] * cscale, hp1, lp1);
                *(uint32_t*)(Ch + (size_t)m0 * DIMK + n0)       = hp0;
                *(uint32_t*)(Ch + (size_t)(m0 + 8) * DIMK + n0) = hp1;
                *(uint32_t*)(Cl + (size_t)m0 * DIMK + n0)       = lp0;
                *(uint32_t*)(Cl + (size_t)(m0 + 8) * DIMK + n0) = lp1;
            }
        }
    }
}

__global__ __launch_bounds__(256, 1)
void gemm_qkv_kernel()
{
    extern __shared__ char smem[];
    int z = blockIdx.z;
    const __nv_bfloat16 *Lh, *Ll;
    __nv_bfloat16 *Ch, *Cl;
    float cs;
    if (z == 0)      { Lh = g_lq_h; Ll = g_lq_l; Ch = g_q_h; Cl = g_q_l; cs = QSCALE; }
    else if (z == 1) { Lh = g_lk_h; Ll = g_lk_l; Ch = g_k_h; Cl = g_k_l; cs = 1.f; }
    else             { Lh = g_lv_h; Ll = g_lv_l; Ch = g_v_h; Cl = g_v_l; cs = 1.f; }
    gemm_body(smem, g_xn_h, g_xn_l,
              g_w_h + (size_t)z * DIMK * DIMK, g_w_l + (size_t)z * DIMK * DIMK,
              Lh, Ll, g_b16_h + (size_t)z * DIMK * 16, g_b16_l + (size_t)z * DIMK * 16,
              (float*)0, Ch, Cl, cs);
}

__global__ __launch_bounds__(256, 1)
void gemm_o_kernel(float* __restrict__ out)
{
    extern __shared__ char smem[];
    gemm_body(smem, g_att_h, g_att_l,
              g_w_h + (size_t)3 * DIMK * DIMK, g_w_l + (size_t)3 * DIMK * DIMK,
              g_lo_h, g_lo_l, g_b16_h + (size_t)3 * DIMK * 16, g_b16_l + (size_t)3 * DIMK * 16,
              out, (__nv_bfloat16*)0, (__nv_bfloat16*)0, 1.f);
}

// ---------------- HMMA split-bf16 flash attention, block-causal (frame=256) ----------------
// Champion config (WAIT1 deep prefetch, 1 CTA/SM) made race-free by a trailing
// __syncthreads(): iteration kt's cp.async into buffer (kt+1)&1 is only issued after
// kt-1's trailing barrier sealed all reads of that buffer.
__global__ __launch_bounds__(256, 1)
void attn_mma_kernel()
{
    extern __shared__ char smem[];
    const uint32_t sb = smem_u32(smem);
    int qt = 15 - (int)blockIdx.x;           // big frames first
    int h  = blockIdx.y;
    int b  = blockIdx.z;
    int t0 = qt << 7;
    int ntile = ((qt >> 1) + 1) << 2;        // key tiles of 64
    int tid = threadIdx.x, lane = tid & 31, w = tid >> 5;
    size_t base = ((size_t)b * 2048) * DIMK + h * DHEAD;

    // Q load (hi+lo): 128 rows x 128B each, 2 threads/row
    {
        int lrow = tid >> 1;
        int lsegb = (tid & 1) * 4;
        size_t g = base + (size_t)(t0 + lrow) * DIMK;
        #pragma unroll
        for (int j = 0; j < 4; ++j) {
            int seg = lsegb + j;
            uint32_t so = sb + swz128u((uint32_t)lrow * 128 + seg * 16);
            cpa16(so,         g_q_h + g + seg * 8);
            cpa16(so + 16384, g_q_l + g + seg * 8);
        }
    }
    auto load_kv = [&](int kt, int st) {
        uint32_t sv = sb + 32768 + (uint32_t)st * 32768;
        int lrow = tid >> 2;
        int lsegb = (tid & 3) * 2;
        size_t g = base + (size_t)((kt << 6) + lrow) * DIMK;
        #pragma unroll
        for (int j = 0; j < 2; ++j) {
            int seg = lsegb + j;
            uint32_t so = sv + swz128u((uint32_t)lrow * 128 + seg * 16);
            cpa16(so,         g_k_h + g + seg * 8);
            cpa16(so + 8192,  g_k_l + g + seg * 8);
            cpa16(so + 16384, g_v_h + g + seg * 8);
            cpa16(so + 24576, g_v_l + g + seg * 8);
        }
    };

    const int rA = w * 16 + (lane & 15);
    const uint32_t qRow = (uint32_t)rA * 128;
    const uint32_t qXor = (uint32_t)((rA & 7) << 4);
    const uint32_t aK = (uint32_t)((lane >> 4) << 4);
    uint32_t kRow[4], kXor[4];
    #pragma unroll
    for (int np = 0; np < 4; ++np) {
        int rB = np * 16 + ((lane >> 4) & 1) * 8 + (lane & 7);
        kRow[np] = (uint32_t)rB * 128;
        kXor[np] = (uint32_t)((rB & 7) << 4);
    }
    const uint32_t bK = (uint32_t)(((lane >> 3) & 1) * 16);
    const int keyB = ((lane >> 3) & 1) * 8 + (lane & 7);
    const int dhB  = ((lane >> 4) & 1) * 8;
    const uint32_t vXor = (uint32_t)((lane & 7) << 4);

    float accO[8][4];
    #pragma unroll
    for (int nt = 0; nt < 8; ++nt)
        #pragma unroll
        for (int i = 0; i < 4; ++i) accO[nt][i] = 0.f;
    float mreg[2] = {-1e30f, -1e30f};
    float lreg[2] = {0.f, 0.f};

    load_kv(0, 0); CP_COMMIT();

    #pragma unroll 1
    for (int kt = 0; kt < ntile; ++kt) {
        if (kt + 1 < ntile) { load_kv(kt + 1, (kt + 1) & 1); CP_COMMIT(); CP_WAIT1(); }
        else                { CP_WAIT0(); }
        __syncthreads();
        uint32_t kb = sb + 32768 + (uint32_t)(kt & 1) * 32768;
        uint32_t vb = kb + 16384;

        // S = QK^T (3-term split)
        float s[8][4];
        #pragma unroll
        for (int nt = 0; nt < 8; ++nt)
            #pragma unroll
            for (int i = 0; i < 4; ++i) s[nt][i] = 0.f;
        #pragma unroll
        for (int ks = 0; ks < 4; ++ks) {
            uint32_t kbyte = (uint32_t)ks * 32;
            uint32_t ah[4], al[4], bh[4][4], bl[4][4];
            uint32_t ad = sb + ((qRow + kbyte + aK) ^ qXor);
            ldsm4(ah, ad);
            ldsm4(al, ad + 16384);
            #pragma unroll
            for (int np = 0; np < 4; ++np) {
                uint32_t bd = kb + ((kRow[np] + kbyte + bK) ^ kXor[np]);
                ldsm4(bh[np], bd);
                ldsm4(bl[np], bd + 8192);
            }
            #pragma unroll
            for (int np = 0; np < 4; ++np)
                #pragma unroll
                for (int hf = 0; hf < 2; ++hf) {
                    float* cc = s[np * 2 + hf];
                    mma16816(cc, ah, &bh[np][hf * 2]);
                    mma16816(cc, ah, &bl[np][hf * 2]);
                    mma16816(cc, al, &bh[np][hf * 2]);
                }
        }

        // online softmax in exp2 domain (logits pre-scaled via QSCALE in q)
        #pragma unroll
        for (int i = 0; i < 2; ++i) {
            float mx = -1e30f;
            #pragma unroll
            for (int nt = 0; nt < 8; ++nt)
                mx = fmaxf(mx, fmaxf(s[nt][2*i], s[nt][2*i+1]));
            mx = fmaxf(mx, __shfl_xor_sync(0xffffffffu, mx, 1));
            mx = fmaxf(mx, __shfl_xor_sync(0xffffffffu, mx, 2));
            float mnew = fmaxf(mreg[i], mx);
            float corr = ex2f(mreg[i] - mnew);
            mreg[i] = mnew;
            float rs = 0.f;
            #pragma unroll
            for (int nt = 0; nt < 8; ++nt) {
                float p0 = ex2f(s[nt][2*i]   - mnew);
                float p1 = ex2f(s[nt][2*i+1] - mnew);
                s[nt][2*i] = p0; s[nt][2*i+1] = p1;
                rs += p0 + p1;
            }
            rs += __shfl_xor_sync(0xffffffffu, rs, 1);
            rs += __shfl_xor_sync(0xffffffffu, rs, 2);
            lreg[i] = lreg[i] * corr + rs;
            #pragma unroll
            for (int nt = 0; nt < 8; ++nt) {
                accO[nt][2*i]   *= corr;
                accO[nt][2*i+1] *= corr;
            }
        }

        // O += P V (3-term split); pack P per kp to limit liveness
        #pragma unroll
        for (int kp = 0; kp < 4; ++kp) {
            uint32_t paH[4], paL[4];
            #pragma unroll
            for (int q4 = 0; q4 < 4; ++q4) {
                int nt = kp * 2 + (q4 >> 1);
                int e0 = (q4 & 1) * 2;
                split2(s[nt][e0], s[nt][e0 + 1], paH[q4], paL[q4]);
            }
            uint32_t vrow = (uint32_t)(kp * 16 + keyB) * 128;
            uint32_t vbh[4][4], vbl[4][4];
            #pragma unroll
            for (int np = 0; np < 4; ++np) {
                uint32_t bd = vb + ((vrow + (uint32_t)(np * 16 + dhB) * 2) ^ vXor);
                ldsm4t(vbh[np], bd);
                ldsm4t(vbl[np], bd + 8192);
            }
            #pragma unroll
            for (int np = 0; np < 4; ++np)
                #pragma unroll
                for (int hf = 0; hf < 2; ++hf) {
                    float* cc = accO[np * 2 + hf];
                    mma16816(cc, paH, &vbh[np][hf * 2]);
                    mma16816(cc, paH, &vbl[np][hf * 2]);
                    mma16816(cc, paL, &vbh[np][hf * 2]);
                }
        }
        __syncthreads();   // seal all reads of this stage before next iteration overwrites it
    }

    // epilogue: hi/lo bf16 att only
    #pragma unroll
    for (int i = 0; i < 2; ++i) {
        float inv = 1.0f / lreg[i];
        int row = t0 + w * 16 + (lane >> 2) + i * 8;
        size_t rb = base + (size_t)row * DIMK;
        #pragma unroll
        for (int nt = 0; nt < 8; ++nt) {
            int col = nt * 8 + (lane & 3) * 2;
            float f0 = accO[nt][2*i] * inv, f1 = accO[nt][2*i+1] * inv;
            uint32_t hp, lp;
            split2(f0, f1, hp, lp);
            *(uint32_t*)(g_att_h + rb + col) = hp;
            *(uint32_t*)(g_att_l + rb + col) = lp;
        }
    }
}

// ---------------- launch ----------------
extern "C" void kernel_launch(void* const* d_in, const int* in_sizes, int n_in,
                              void* d_out, int out_size)
{
    (void)in_sizes; (void)n_in; (void)out_size;
    const float* x      = (const float*)d_in[0];
    const float* m_tok  = (const float*)d_in[1];
    const float* norm_g = (const float*)d_in[2];
    const float* norm_b = (const float*)d_in[3];
    const float* mnorm_g= (const float*)d_in[4];
    const float* mnorm_b= (const float*)d_in[5];
    const float* Wq = (const float*)d_in[6];
    const float* Aq = (const float*)d_in[7];
    const float* Bq = (const float*)d_in[8];
    const float* Gq = (const float*)d_in[9];
    const float* Wk = (const float*)d_in[10];
    const float* Ak = (const float*)d_in[11];
    const float* Bk = (const float*)d_in[12];
    const float* Gk = (const float*)d_in[13];
    const float* Wv = (const float*)d_in[14];
    const float* Av = (const float*)d_in[15];
    const float* Bv = (const float*)d_in[16];
    const float* Gv = (const float*)d_in[17];
    const float* Wo = (const float*)d_in[18];
    const float* Ao = (const float*)d_in[19];
    const float* Bo = (const float*)d_in[20];
    const float* Go = (const float*)d_in[21];
    float* out = (float*)d_out;

    __nv_bfloat16 *p_xnh, *p_xnl, *p_mnh, *p_mnl;
    cudaGetSymbolAddress((void**)&p_xnh, g_xn_h);
    cudaGetSymbolAddress((void**)&p_xnl, g_xn_l);
    cudaGetSymbolAddress((void**)&p_mnh, g_mn_h);
    cudaGetSymbolAddress((void**)&p_mnl, g_mn_l);

    const int GSMEM = 2 * 65536 + 4 * 6144;        // 152 KB
    const int ASMEM = 32768 + 2 * 32768;           // 96 KB
    const int RSMEM = 2 * 40960;                   // 80 KB
    cudaFuncSetAttribute(gemm_qkv_kernel, cudaFuncAttributeMaxDynamicSharedMemorySize, GSMEM);
    cudaFuncSetAttribute(gemm_o_kernel,   cudaFuncAttributeMaxDynamicSharedMemorySize, GSMEM);
    cudaFuncSetAttribute(attn_mma_kernel, cudaFuncAttributeMaxDynamicSharedMemorySize, ASMEM);
    cudaFuncSetAttribute(lr_xm_kernel,    cudaFuncAttributeMaxDynamicSharedMemorySize, RSMEM);
    cudaFuncSetAttribute(lr_o_kernel,     cudaFuncAttributeMaxDynamicSharedMemorySize, RSMEM);

    cvt_w4_kernel<<<dim3(1024, 4), 256>>>(Wq, Wk, Wv, Wo);
    cvt_b4_kernel<<<dim3(4, 4), 256>>>(Bq, Bk, Bv, Bo);
    cvt_vec_kernel<<<dim3(32, 3), 256>>>(Aq, Ak, Av, Gq, Gk, Gv, Go, Ao);

    ln2_kernel<<<dim3(NTOK, 2), 256>>>(x, norm_g, norm_b, p_xnh, p_xnl,
                                       m_tok, mnorm_g, mnorm_b, p_mnh, p_mnl);

    lr_xm_kernel<<<dim3(32, 2), 256, RSMEM>>>();
    combine_qkv_kernel<<<256, 256>>>();

    gemm_qkv_kernel<<<dim3(8, 32, 3), 256, GSMEM>>>();

    attn_mma_kernel<<<dim3(16, 16, 2), 256, ASMEM>>>();

    lr_o_kernel<<<32, 256, RSMEM>>>();
    combine_o_kernel<<<256, 256>>>();
    gemm_o_kernel<<<dim3(8, 32), 256, GSMEM>>>(out);
}

// round 16
// speedup vs baseline: 1.0462x; 1.0007x over previous
#include <cuda_runtime.h>
#include <cuda_bf16.h>
#include <math.h>
#include <stdint.h>

#define NTOK 4096            // B*T
#define DIMK 1024
#define NHEAD 16
#define DHEAD 64

// 0.125 * log2(e): folded into q so softmax is exp2(s - m)
#define QSCALE 0.18033688011112042f

// ---------------- scratch (device globals; no allocs allowed) ----------------
__device__ float g_go  [NTOK * 8];
__device__ float g_resx[NTOK * 32];
__device__ float g_resm[NTOK * 32];

__device__ __nv_bfloat16 g_xn_h [NTOK * DIMK];
__device__ __nv_bfloat16 g_xn_l [NTOK * DIMK];
__device__ __nv_bfloat16 g_mn_h [NTOK * DIMK];
__device__ __nv_bfloat16 g_mn_l [NTOK * DIMK];
__device__ __nv_bfloat16 g_q_h  [NTOK * DIMK];
__device__ __nv_bfloat16 g_q_l  [NTOK * DIMK];
__device__ __nv_bfloat16 g_k_h  [NTOK * DIMK];
__device__ __nv_bfloat16 g_k_l  [NTOK * DIMK];
__device__ __nv_bfloat16 g_v_h  [NTOK * DIMK];
__device__ __nv_bfloat16 g_v_l  [NTOK * DIMK];
__device__ __nv_bfloat16 g_att_h[NTOK * DIMK];
__device__ __nv_bfloat16 g_att_l[NTOK * DIMK];
__device__ __nv_bfloat16 g_w_h  [4 * DIMK * DIMK];
__device__ __nv_bfloat16 g_w_l  [4 * DIMK * DIMK];
__device__ __nv_bfloat16 g_b16_h[4 * DIMK * 16];
__device__ __nv_bfloat16 g_b16_l[4 * DIMK * 16];
__device__ __nv_bfloat16 g_ax_h [32 * DIMK];
__device__ __nv_bfloat16 g_ax_l [32 * DIMK];
__device__ __nv_bfloat16 g_gm_h [32 * DIMK];
__device__ __nv_bfloat16 g_gm_l [32 * DIMK];
__device__ __nv_bfloat16 g_ao_h [32 * DIMK];
__device__ __nv_bfloat16 g_ao_l [32 * DIMK];
__device__ __nv_bfloat16 g_lq_h [NTOK * 16];
__device__ __nv_bfloat16 g_lq_l [NTOK * 16];
__device__ __nv_bfloat16 g_lk_h [NTOK * 16];
__device__ __nv_bfloat16 g_lk_l [NTOK * 16];
__device__ __nv_bfloat16 g_lv_h [NTOK * 16];
__device__ __nv_bfloat16 g_lv_l [NTOK * 16];
__device__ __nv_bfloat16 g_lo_h [NTOK * 16];
__device__ __nv_bfloat16 g_lo_l [NTOK * 16];

// ---------------- helpers ----------------
__device__ __forceinline__ uint32_t smem_u32(const void* p) {
    uint32_t a;
    asm("{ .reg .u64 t; cvta.to.shared.u64 t, %1; cvt.u32.u64 %0, t; }" : "=r"(a) : "l"(p));
    return a;
}

__device__ __forceinline__ void cpa16(uint32_t s, const void* g) {
    asm volatile("cp.async.cg.shared.global [%0], [%1], 16;" :: "r"(s), "l"(g));
}
#define CP_COMMIT() asm volatile("cp.async.commit_group;" ::: "memory")
#define CP_WAIT1()  asm volatile("cp.async.wait_group 1;" ::: "memory")
#define CP_WAIT0()  asm volatile("cp.async.wait_group 0;" ::: "memory")

__device__ __forceinline__ void ldsm4(uint32_t* r, uint32_t addr) {
    asm volatile("ldmatrix.sync.aligned.m8n8.x4.shared.b16 {%0,%1,%2,%3}, [%4];"
        : "=r"(r[0]), "=r"(r[1]), "=r"(r[2]), "=r"(r[3]) : "r"(addr));
}
__device__ __forceinline__ void ldsm4t(uint32_t* r, uint32_t addr) {
    asm volatile("ldmatrix.sync.aligned.m8n8.x4.trans.shared.b16 {%0,%1,%2,%3}, [%4];"
        : "=r"(r[0]), "=r"(r[1]), "=r"(r[2]), "=r"(r[3]) : "r"(addr));
}

__device__ __forceinline__ void mma16816(float* c, const uint32_t* a, const uint32_t* b) {
    asm volatile(
        "mma.sync.aligned.m16n8k16.row.col.f32.bf16.bf16.f32 "
        "{%0,%1,%2,%3}, {%4,%5,%6,%7}, {%8,%9}, {%0,%1,%2,%3};"
        : "+f"(c[0]), "+f"(c[1]), "+f"(c[2]), "+f"(c[3])
        : "r"(a[0]), "r"(a[1]), "r"(a[2]), "r"(a[3]), "r"(b[0]), "r"(b[1]));
}

__device__ __forceinline__ uint32_t swz128u(uint32_t o) { return o ^ ((o >> 3) & 0x70); }

__device__ __forceinline__ void splitf(float x, __nv_bfloat16& h, __nv_bfloat16& l) {
    h = __float2bfloat16(x);
    l = __float2bfloat16(x - __bfloat162float(h));
}
__device__ __forceinline__ uint32_t packbf(float f0, float f1) {
    uint32_t r;
    asm("cvt.rn.bf16x2.f32 %0, %1, %2;" : "=r"(r) : "f"(f1), "f"(f0));
    return r;
}
__device__ __forceinline__ void split2(float f0, float f1, uint32_t& hp, uint32_t& lp) {
    hp = packbf(f0, f1);
    float h0 = __uint_as_float(hp << 16);
    float h1 = __uint_as_float(hp & 0xffff0000u);
    lp = packbf(f0 - h0, f1 - h1);
}
__device__ __forceinline__ float ex2f(float x) {
    float r;
    asm("ex2.approx.f32 %0, %1;" : "=f"(r) : "f"(x));
    return r;
}

// ---------------- LayerNorm (x and m_tok in one launch; hi/lo bf16 outputs only) ----------------
__global__ void ln2_kernel(const float* __restrict__ in0, const float* __restrict__ g0,
                           const float* __restrict__ b0,
                           __nv_bfloat16* __restrict__ hi0, __nv_bfloat16* __restrict__ lo0,
                           const float* __restrict__ in1, const float* __restrict__ g1,
                           const float* __restrict__ b1,
                           __nv_bfloat16* __restrict__ hi1, __nv_bfloat16* __restrict__ lo1)
{
    int which = blockIdx.y;
    const float* in = which ? in1 : in0;
    const float* g  = which ? g1  : g0;
    const float* b  = which ? b1  : b0;
    __nv_bfloat16* hi = which ? hi1 : hi0;
    __nv_bfloat16* lo = which ? lo1 : lo0;
    int row = blockIdx.x;
    int tid = threadIdx.x;
    float4 a = ((const float4*)(in + (size_t)row * DIMK))[tid];
    float s = a.x + a.y + a.z + a.w;
    float q = a.x*a.x + a.y*a.y + a.z*a.z + a.w*a.w;
    #pragma unroll
    for (int o = 16; o; o >>= 1) {
        s += __shfl_xor_sync(0xffffffffu, s, o);
        q += __shfl_xor_sync(0xffffffffu, q, o);
    }
    __shared__ float ss[8], sq[8];
    __shared__ float s_mean, s_rstd;
    int warp = tid >> 5, lane = tid & 31;
    if (lane == 0) { ss[warp] = s; sq[warp] = q; }
    __syncthreads();
    if (tid == 0) {
        float ts = 0.f, tq = 0.f;
        #pragma unroll
        for (int i = 0; i < 8; i++) { ts += ss[i]; tq += sq[i]; }
        float mean = ts * (1.0f / DIMK);
        float var  = tq * (1.0f / DIMK) - mean * mean;
        s_mean = mean;
        s_rstd = rsqrtf(var + 1e-5f);
    }
    __syncthreads();
    float mean = s_mean, rstd = s_rstd;
    float4 gg = ((const float4*)g)[tid];
    float4 bb = ((const float4*)b)[tid];
    float4 r;
    r.x = (a.x - mean) * rstd * gg.x + bb.x;
    r.y = (a.y - mean) * rstd * gg.y + bb.y;
    r.z = (a.z - mean) * rstd * gg.z + bb.z;
    r.w = (a.w - mean) * rstd * gg.w + bb.w;
    uint32_t h0, l0, h1, l1;
    split2(r.x, r.y, h0, l0);
    split2(r.z, r.w, h1, l1);
    ((uint32_t*)(hi + (size_t)row * DIMK))[tid*2]   = h0;
    ((uint32_t*)(hi + (size_t)row * DIMK))[tid*2+1] = h1;
    ((uint32_t*)(lo + (size_t)row * DIMK))[tid*2]   = l0;
    ((uint32_t*)(lo + (size_t)row * DIMK))[tid*2+1] = l1;
}

// ---------------- fp32 -> hi/lo bf16 weight conversion (all 4 slots, one launch) ----------------
__global__ void cvt_w4_kernel(const float* __restrict__ w0, const float* __restrict__ w1,
                              const float* __restrict__ w2, const float* __restrict__ w3)
{
    int slot = blockIdx.y;
    const float* in = (slot == 0) ? w0 : (slot == 1) ? w1 : (slot == 2) ? w2 : w3;
    size_t i = (size_t)blockIdx.x * blockDim.x + threadIdx.x;
    float4 v = ((const float4*)in)[i];
    uint32_t hA, lA, hB, lB;
    split2(v.x, v.y, hA, lA);
    split2(v.z, v.w, hB, lB);
    size_t o = (size_t)slot * DIMK * DIMK + i * 4;
    *(uint32_t*)(g_w_h + o)     = hA;
    *(uint32_t*)(g_w_h + o + 2) = hB;
    *(uint32_t*)(g_w_l + o)     = lA;
    *(uint32_t*)(g_w_l + o + 2) = lB;
}

// ---------------- B pads + A/G/Ao vectors, one launch ----------------
// blocks [0,16):  B[N,8] -> padded [N,16] hi/lo (slot = bx>>2, 256 rows per block)
// blocks [16,112): A/G/Ao rows -> padded [32,1024] hi/lo (mat = (bx-16)/32, r = (bx-16)%32)
__global__ void cvt_bv_kernel(const float* __restrict__ b0, const float* __restrict__ b1,
                              const float* __restrict__ b2, const float* __restrict__ b3,
                              const float* __restrict__ Aq, const float* __restrict__ Ak,
                              const float* __restrict__ Av, const float* __restrict__ Gq,
                              const float* __restrict__ Gk, const float* __restrict__ Gv,
                              const float* __restrict__ Go, const float* __restrict__ Ao)
{
    int bx = blockIdx.x;
    int tid = threadIdx.x;
    if (bx < 16) {
        int slot = bx >> 2;
        const float* B = (slot == 0) ? b0 : (slot == 1) ? b1 : (slot == 2) ? b2 : b3;
        int r = (bx & 3) * 256 + tid;
        size_t o = (size_t)slot * DIMK * 16 + (size_t)r * 16;
        __nv_bfloat16 z = __float2bfloat16(0.f);
        #pragma unroll
        for (int j = 0; j < 8; j++) {
            __nv_bfloat16 h, l;
            splitf(B[r * 8 + j], h, l);
            g_b16_h[o + j] = h; g_b16_l[o + j] = l;
            g_b16_h[o + 8 + j] = z; g_b16_l[o + 8 + j] = z;
        }
    } else {
        int idx = bx - 16;
        int mat = idx >> 5;
        int r = idx & 31;
        const float* src = 0;
        __nv_bfloat16 *dh, *dl;
        if (mat == 0) {
            dh = g_ax_h; dl = g_ax_l;
            if (r < 8) src = Aq + r * DIMK;
            else if (r < 16) src = Ak + (r - 8) * DIMK;
            else if (r < 24) src = Av + (r - 16) * DIMK;
        } else if (mat == 1) {
            dh = g_gm_h; dl = g_gm_l;
            if (r < 8) src = Gq + r * DIMK;
            else if (r < 16) src = Gk + (r - 8) * DIMK;
            else if (r < 24) src = Gv + (r - 16) * DIMK;
            else src = Go + (r - 24) * DIMK;
        } else {
            dh = g_ao_h; dl = g_ao_l;
            if (r < 8) src = Ao + r * DIMK;
        }
        float4 v = src ? ((const float4*)src)[tid] : make_float4(0.f, 0.f, 0.f, 0.f);
        uint32_t hA, lA, hB, lB;
        split2(v.x, v.y, hA, lA);
        split2(v.z, v.w, hB, lB);
        size_t o = (size_t)r * DIMK + (size_t)tid * 4;
        *(uint32_t*)(dh + o)     = hA;
        *(uint32_t*)(dh + o + 2) = hB;
        *(uint32_t*)(dl + o)     = lA;
        *(uint32_t*)(dl + o + 2) = lB;
    }
}

// ---------------- thin split-bf16 GEMM core: acc[4][4] += X128[.,1024] . V[32,1024]^T ----------------
// 256 threads. Stage s at s*40960: Ah+0, Al+16384, Bh+32768, Bl+36864.
__device__ __forceinline__
void lr_accum(char* smem,
              const __nv_bfloat16* __restrict__ Xh, const __nv_bfloat16* __restrict__ Xl,
              const __nv_bfloat16* __restrict__ Vh, const __nv_bfloat16* __restrict__ Vl,
              int bm, float acc[4][4])
{
    const uint32_t sb = smem_u32(smem);
    const int tid = threadIdx.x;
    const int lane = tid & 31, w = tid >> 5;

    const int ar = tid >> 1, asg = (tid & 1) * 4;
    const int br = (tid & 63) >> 1, bsg = (tid & 1) * 4;
    auto load_stage = [&](int c, int s) {
        uint32_t sbase = sb + (uint32_t)s * 40960;
        size_t offx = (size_t)(bm + ar) * DIMK + c * 64;
        #pragma unroll
        for (int j = 0; j < 4; ++j) {
            int seg = asg + j;
            uint32_t so = sbase + swz128u((uint32_t)ar * 128 + seg * 16);
            cpa16(so,         Xh + offx + seg * 8);
            cpa16(so + 16384, Xl + offx + seg * 8);
        }
        if (tid < 64) {
            size_t offv = (size_t)br * DIMK + c * 64;
            #pragma unroll
            for (int j = 0; j < 4; ++j) {
                int seg = bsg + j;
                uint32_t so = sbase + 32768 + swz128u((uint32_t)br * 128 + seg * 16);
                cpa16(so,        Vh + offv + seg * 8);
                cpa16(so + 4096, Vl + offv + seg * 8);
            }
        }
    };

    const int rA = w * 16 + (lane & 15);
    const uint32_t aRow = (uint32_t)rA * 128;
    const uint32_t aXor = (uint32_t)((rA & 7) << 4);
    const uint32_t aK = (uint32_t)((lane >> 4) << 4);
    uint32_t bRow[2], bXor[2];
    #pragma unroll
    for (int np = 0; np < 2; ++np) {
        int rB = np * 16 + ((lane >> 4) & 1) * 8 + (lane & 7);
        bRow[np] = (uint32_t)rB * 128;
        bXor[np] = (uint32_t)((rB & 7) << 4);
    }
    const uint32_t bK = (uint32_t)(((lane >> 3) & 1) * 16);

    load_stage(0, 0); CP_COMMIT();
    #pragma unroll 1
    for (int c = 0; c < 16; ++c) {
        CP_WAIT0();
        __syncthreads();
        if (c + 1 < 16) { load_stage(c + 1, (c + 1) & 1); CP_COMMIT(); }
        uint32_t sbase = sb + (uint32_t)(c & 1) * 40960;
        #pragma unroll
        for (int ks = 0; ks < 4; ++ks) {
            uint32_t kb = (uint32_t)ks * 32;
            uint32_t ah[4], al[4];
            uint32_t ad = sbase + ((aRow + kb + aK) ^ aXor);
            ldsm4(ah, ad);
            ldsm4(al, ad + 16384);
            #pragma unroll
            for (int np = 0; np < 2; ++np) {
                uint32_t bh[4], bl[4];
                uint32_t bd = sbase + 32768 + ((bRow[np] + kb + bK) ^ bXor[np]);
                ldsm4(bh, bd);
                ldsm4(bl, bd + 4096);
                #pragma unroll
                for (int hf = 0; hf < 2; ++hf) {
                    float* cc = acc[np * 2 + hf];
                    mma16816(cc, ah, &bh[hf * 2]);
                    mma16816(cc, ah, &bl[hf * 2]);
                    mma16816(cc, al, &bh[hf * 2]);
                }
            }
        }
        __syncthreads();
    }
}

// x/m low-rank projections -> g_resx / g_resm (separate grids; max parallelism)
__global__ __launch_bounds__(256, 2)
void lr_xm_kernel()
{
    extern __shared__ char smem[];
    const int tid = threadIdx.x;
    const int lane = tid & 31, w = tid >> 5;
    const int bm = blockIdx.x * 128;
    float acc[4][4];
    #pragma unroll
    for (int nt = 0; nt < 4; ++nt)
        #pragma unroll
        for (int i = 0; i < 4; ++i) acc[nt][i] = 0.f;
    float* out;
    if (blockIdx.y == 0) { lr_accum(smem, g_xn_h, g_xn_l, g_ax_h, g_ax_l, bm, acc); out = g_resx; }
    else                 { lr_accum(smem, g_mn_h, g_mn_l, g_gm_h, g_gm_l, bm, acc); out = g_resm; }
    int m0 = bm + w * 16 + (lane >> 2);
    #pragma unroll
    for (int nt = 0; nt < 4; ++nt) {
        int n0 = nt * 8 + (lane & 3) * 2;
        *(float2*)(out + (size_t)m0 * 32 + n0)       = make_float2(acc[nt][0], acc[nt][1]);
        *(float2*)(out + (size_t)(m0 + 8) * 32 + n0) = make_float2(acc[nt][2], acc[nt][3]);
    }
}

// o low-rank projection with FUSED combine: lo = 0.25 * (att.Ao^T) * go, direct hi/lo output
__global__ __launch_bounds__(256, 2)
void lr_o_kernel()
{
    extern __shared__ char smem[];
    const int tid = threadIdx.x;
    const int lane = tid & 31, w = tid >> 5;
    const int bm = blockIdx.x * 128;
    float acc[4][4];
    #pragma unroll
    for (int nt = 0; nt < 4; ++nt)
        #pragma unroll
        for (int i = 0; i < 4; ++i) acc[nt][i] = 0.f;
    lr_accum(smem, g_att_h, g_att_l, g_ao_h, g_ao_l, bm, acc);

    #pragma unroll
    for (int i = 0; i < 2; ++i) {
        int m = bm + w * 16 + (lane >> 2) + i * 8;
        #pragma unroll
        for (int nt = 0; nt < 4; ++nt) {
            int n0 = nt * 8 + (lane & 3) * 2;
            if (n0 < 8) {
                float2 go = *(const float2*)(g_go + (size_t)m * 8 + n0);
                uint32_t hp, lp;
                split2(0.25f * acc[nt][2*i] * go.x, 0.25f * acc[nt][2*i+1] * go.y, hp, lp);
                *(uint32_t*)(g_lo_h + (size_t)m * 16 + n0) = hp;
                *(uint32_t*)(g_lo_l + (size_t)m * 16 + n0) = lp;
                *(uint32_t*)(g_lo_h + (size_t)m * 16 + n0 + 8) = 0u;
                *(uint32_t*)(g_lo_l + (size_t)m * 16 + n0 + 8) = 0u;
            }
        }
    }
}

// ---------------- combine: low-rank activations + gates (qkv path) ----------------
__global__ void combine_qkv_kernel()
{
    int idx = blockIdx.x * blockDim.x + threadIdx.x;
    int t = idx >> 4, j = idx & 15;
    float vq = 0.f, vk = 0.f, vv = 0.f;
    if (j < 8) {
        const float* rx = g_resx + (size_t)t * 32;
        const float* rm = g_resm + (size_t)t * 32;
        vq = 0.25f * rx[j]      * rm[j];
        vk = 0.25f * rx[8 + j]  * rm[8 + j];
        vv = 0.25f * rx[16 + j] * rm[16 + j];
        g_go[t * 8 + j] = rm[24 + j];
    }
    __nv_bfloat16 h, l;
    splitf(vq, h, l); g_lq_h[t*16 + j] = h; g_lq_l[t*16 + j] = l;
    splitf(vk, h, l); g_lk_h[t*16 + j] = h; g_lk_l[t*16 + j] = l;
    splitf(vv, h, l); g_lv_h[t*16 + j] = h; g_lv_l[t*16 + j] = l;
}

// ---------------- HMMA split-bf16 GEMM body + folded rank-8 LoRA (champion config) ----------------
__device__ __forceinline__
void gemm_body(char* smem,
               const __nv_bfloat16* __restrict__ Xh, const __nv_bfloat16* __restrict__ Xl,
               const __nv_bfloat16* __restrict__ Wh, const __nv_bfloat16* __restrict__ Wl,
               const __nv_bfloat16* __restrict__ Lh, const __nv_bfloat16* __restrict__ Ll,
               const __nv_bfloat16* __restrict__ Bh, const __nv_bfloat16* __restrict__ Bl,
               float* __restrict__ C,
               __nv_bfloat16* __restrict__ Ch, __nv_bfloat16* __restrict__ Cl,
               float cscale)
{
    const uint32_t sb = smem_u32(smem);
    const int tid = threadIdx.x;
    const int lane = tid & 31, w = tid >> 5;
    const int wm = (w & 3) * 32, wn = (w >> 2) * 64;
    const int bm = blockIdx.y * 128, bn = blockIdx.x * 128;

    // LoRA tiles -> smem
    {
        int row = tid >> 1, cs = tid & 1;
        uint32_t so = 131072u + (uint32_t)row * 48 + cs * 16;
        size_t gl = (size_t)(bm + row) * 16 + cs * 8;
        size_t gb = (size_t)(bn + row) * 16 + cs * 8;
        *(int4*)(smem + so)          = *(const int4*)(Lh + gl);
        *(int4*)(smem + so + 6144)   = *(const int4*)(Ll + gl);
        *(int4*)(smem + so + 12288)  = *(const int4*)(Bh + gb);
        *(int4*)(smem + so + 18432)  = *(const int4*)(Bl + gb);
    }

    const int r0 = tid >> 3, seg = tid & 7;
    auto load_stage = [&](int c, int s) {
        uint32_t sbase = sb + (uint32_t)s * 65536;
        #pragma unroll
        for (int j = 0; j < 4; ++j) {
            int row = r0 + j * 32;
            size_t offx = (size_t)(bm + row) * DIMK + c * 64 + seg * 8;
            size_t offw = (size_t)(bn + row) * DIMK + c * 64 + seg * 8;
            uint32_t so = sbase + swz128u((uint32_t)row * 128 + seg * 16);
            cpa16(so,          Xh + offx);
            cpa16(so + 16384,  Xl + offx);
            cpa16(so + 32768,  Wh + offw);
            cpa16(so + 49152,  Wl + offw);
        }
    };

    uint32_t aRow[2], aXor[2];
    #pragma unroll
    for (int mt = 0; mt < 2; ++mt) {
        int rA = wm + mt * 16 + (lane & 15);
        aRow[mt] = (uint32_t)rA * 128;
        aXor[mt] = (uint32_t)((rA & 7) << 4);
    }
    const uint32_t aK = (uint32_t)((lane >> 4) << 4);
    uint32_t bRow[4], bXor[4];
    #pragma unroll
    for (int np = 0; np < 4; ++np) {
        int rB = wn + np * 16 + ((lane >> 4) & 1) * 8 + (lane & 7);
        bRow[np] = (uint32_t)rB * 128;
        bXor[np] = (uint32_t)((rB & 7) << 4);
    }
    const uint32_t bK = (uint32_t)(((lane >> 3) & 1) * 16);

    float acc[2][8][4];
    #pragma unroll
    for (int mt = 0; mt < 2; ++mt)
        #pragma unroll
        for (int nt = 0; nt < 8; ++nt)
            #pragma unroll
            for (int i = 0; i < 4; ++i) acc[mt][nt][i] = 0.f;

    auto compute = [&](int s) {
        uint32_t sbase = sb + (uint32_t)s * 65536;
        #pragma unroll
        for (int ks = 0; ks < 4; ++ks) {
            uint32_t kb = (uint32_t)ks * 32;
            uint32_t ah[2][4], al[2][4], bh[4][4], bl[4][4];
            #pragma unroll
            for (int mt = 0; mt < 2; ++mt) {
                uint32_t ad = sbase + ((aRow[mt] + kb + aK) ^ aXor[mt]);
                ldsm4(ah[mt], ad);
                ldsm4(al[mt], ad + 16384);
            }
            #pragma unroll
            for (int np = 0; np < 4; ++np) {
                uint32_t bd = sbase + 32768 + ((bRow[np] + kb + bK) ^ bXor[np]);
                ldsm4(bh[np], bd);
                ldsm4(bl[np], bd + 16384);
            }
            #pragma unroll
            for (int mt = 0; mt < 2; ++mt)
                #pragma unroll
                for (int np = 0; np < 4; ++np)
                    #pragma unroll
                    for (int hf = 0; hf < 2; ++hf) {
                        float* cc = acc[mt][np * 2 + hf];
                        mma16816(cc, ah[mt], &bh[np][hf * 2]);
                        mma16816(cc, ah[mt], &bl[np][hf * 2]);
                        mma16816(cc, al[mt], &bh[np][hf * 2]);
                    }
        }
    };

    load_stage(0, 0); CP_COMMIT();
    #pragma unroll 1
    for (int c = 0; c < 16; ++c) {
        if (c < 15) { load_stage(c + 1, (c + 1) & 1); CP_COMMIT(); CP_WAIT1(); }
        else        { CP_WAIT0(); }
        __syncthreads();
        compute(c & 1);
        __syncthreads();
    }

    // LoRA k16 step
    {
        uint32_t lb = sb + 131072u;
        uint32_t ah[2][4], al[2][4], bh[4][4], bl[4][4];
        #pragma unroll
        for (int mt = 0; mt < 2; ++mt) {
            uint32_t rA = (uint32_t)(wm + mt * 16 + (lane & 15));
            uint32_t ad = lb + rA * 48 + aK;
            ldsm4(ah[mt], ad);
            ldsm4(al[mt], ad + 6144);
        }
        #pragma unroll
        for (int np = 0; np < 4; ++np) {
            uint32_t rB = (uint32_t)(wn + np * 16 + ((lane >> 4) & 1) * 8 + (lane & 7));
            uint32_t bd = lb + 12288 + rB * 48 + bK;
            ldsm4(bh[np], bd);
            ldsm4(bl[np], bd + 6144);
        }
        #pragma unroll
        for (int mt = 0; mt < 2; ++mt)
            #pragma unroll
            for (int np = 0; np < 4; ++np)
                #pragma unroll
                for (int hf = 0; hf < 2; ++hf) {
                    float* cc = acc[mt][np * 2 + hf];
                    mma16816(cc, ah[mt], &bh[np][hf * 2]);
                    mma16816(cc, ah[mt], &bl[np][hf * 2]);
                    mma16816(cc, al[mt], &bh[np][hf * 2]);
                }
    }

    // epilogue (cscale folded into bf16 outputs; fp32 path unscaled)
    #pragma unroll
    for (int mt = 0; mt < 2; ++mt) {
        int m0 = bm + wm + mt * 16 + (lane >> 2);
        #pragma unroll
        for (int nt = 0; nt < 8; ++nt) {
            int n0 = bn + wn + nt * 8 + (lane & 3) * 2;
            float* a = acc[mt][nt];
            if (C) {
                *(float2*)(C + (size_t)m0 * DIMK + n0)       = make_float2(a[0], a[1]);
                *(float2*)(C + (size_t)(m0 + 8) * DIMK + n0) = make_float2(a[2], a[3]);
            }
            if (Ch) {
                uint32_t hp0, lp0, hp1, lp1;
                split2(a[0] * cscale, a[1] * cscale, hp0, lp0);
                split2(a[2] * cscale, a[3] * cscale, hp1, lp1);
                *(uint32_t*)(Ch + (size_t)m0 * DIMK + n0)       = hp0;
                *(uint32_t*)(Ch + (size_t)(m0 + 8) * DIMK + n0) = hp1;
                *(uint32_t*)(Cl + (size_t)m0 * DIMK + n0)       = lp0;
                *(uint32_t*)(Cl + (size_t)(m0 + 8) * DIMK + n0) = lp1;
            }
        }
    }
}

__global__ __launch_bounds__(256, 1)
void gemm_qkv_kernel()
{
    extern __shared__ char smem[];
    int z = blockIdx.z;
    const __nv_bfloat16 *Lh, *Ll;
    __nv_bfloat16 *Ch, *Cl;
    float cs;
    if (z == 0)      { Lh = g_lq_h; Ll = g_lq_l; Ch = g_q_h; Cl = g_q_l; cs = QSCALE; }
    else if (z == 1) { Lh = g_lk_h; Ll = g_lk_l; Ch = g_k_h; Cl = g_k_l; cs = 1.f; }
    else             { Lh = g_lv_h; Ll = g_lv_l; Ch = g_v_h; Cl = g_v_l; cs = 1.f; }
    gemm_body(smem, g_xn_h, g_xn_l,
              g_w_h + (size_t)z * DIMK * DIMK, g_w_l + (size_t)z * DIMK * DIMK,
              Lh, Ll, g_b16_h + (size_t)z * DIMK * 16, g_b16_l + (size_t)z * DIMK * 16,
              (float*)0, Ch, Cl, cs);
}

__global__ __launch_bounds__(256, 1)
void gemm_o_kernel(float* __restrict__ out)
{
    extern __shared__ char smem[];
    gemm_body(smem, g_att_h, g_att_l,
              g_w_h + (size_t)3 * DIMK * DIMK, g_w_l + (size_t)3 * DIMK * DIMK,
              g_lo_h, g_lo_l, g_b16_h + (size_t)3 * DIMK * 16, g_b16_l + (size_t)3 * DIMK * 16,
              out, (__nv_bfloat16*)0, (__nv_bfloat16*)0, 1.f);
}

// ---------------- HMMA split-bf16 flash attention, block-causal (frame=256) ----------------
// WAIT1 deep prefetch, 1 CTA/SM, race-free via trailing __syncthreads().
__global__ __launch_bounds__(256, 1)
void attn_mma_kernel()
{
    extern __shared__ char smem[];
    const uint32_t sb = smem_u32(smem);
    int qt = 15 - (int)blockIdx.x;           // big frames first
    int h  = blockIdx.y;
    int b  = blockIdx.z;
    int t0 = qt << 7;
    int ntile = ((qt >> 1) + 1) << 2;        // key tiles of 64
    int tid = threadIdx.x, lane = tid & 31, w = tid >> 5;
    size_t base = ((size_t)b * 2048) * DIMK + h * DHEAD;

    // Q load (hi+lo): 128 rows x 128B each, 2 threads/row
    {
        int lrow = tid >> 1;
        int lsegb = (tid & 1) * 4;
        size_t g = base + (size_t)(t0 + lrow) * DIMK;
        #pragma unroll
        for (int j = 0; j < 4; ++j) {
            int seg = lsegb + j;
            uint32_t so = sb + swz128u((uint32_t)lrow * 128 + seg * 16);
            cpa16(so,         g_q_h + g + seg * 8);
            cpa16(so + 16384, g_q_l + g + seg * 8);
        }
    }
    auto load_kv = [&](int kt, int st) {
        uint32_t sv = sb + 32768 + (uint32_t)st * 32768;
        int lrow = tid >> 2;
        int lsegb = (tid & 3) * 2;
        size_t g = base + (size_t)((kt << 6) + lrow) * DIMK;
        #pragma unroll
        for (int j = 0; j < 2; ++j) {
            int seg = lsegb + j;
            uint32_t so = sv + swz128u((uint32_t)lrow * 128 + seg * 16);
            cpa16(so,         g_k_h + g + seg * 8);
            cpa16(so + 8192,  g_k_l + g + seg * 8);
            cpa16(so + 16384, g_v_h + g + seg * 8);
            cpa16(so + 24576, g_v_l + g + seg * 8);
        }
    };

    const int rA = w * 16 + (lane & 15);
    const uint32_t qRow = (uint32_t)rA * 128;
    const uint32_t qXor = (uint32_t)((rA & 7) << 4);
    const uint32_t aK = (uint32_t)((lane >> 4) << 4);
    uint32_t kRow[4], kXor[4];
    #pragma unroll
    for (int np = 0; np < 4; ++np) {
        int rB = np * 16 + ((lane >> 4) & 1) * 8 + (lane & 7);
        kRow[np] = (uint32_t)rB * 128;
        kXor[np] = (uint32_t)((rB & 7) << 4);
    }
    const uint32_t bK = (uint32_t)(((lane >> 3) & 1) * 16);
    const int keyB = ((lane >> 3) & 1) * 8 + (lane & 7);
    const int dhB  = ((lane >> 4) & 1) * 8;
    const uint32_t vXor = (uint32_t)((lane & 7) << 4);

    float accO[8][4];
    #pragma unroll
    for (int nt = 0; nt < 8; ++nt)
        #pragma unroll
        for (int i = 0; i < 4; ++i) accO[nt][i] = 0.f;
    float mreg[2] = {-1e30f, -1e30f};
    float lreg[2] = {0.f, 0.f};

    load_kv(0, 0); CP_COMMIT();

    #pragma unroll 1
    for (int kt = 0; kt < ntile; ++kt) {
        if (kt + 1 < ntile) { load_kv(kt + 1, (kt + 1) & 1); CP_COMMIT(); CP_WAIT1(); }
        else                { CP_WAIT0(); }
        __syncthreads();
        uint32_t kb = sb + 32768 + (uint32_t)(kt & 1) * 32768;
        uint32_t vb = kb + 16384;

        // S = QK^T (3-term split)
        float s[8][4];
        #pragma unroll
        for (int nt = 0; nt < 8; ++nt)
            #pragma unroll
            for (int i = 0; i < 4; ++i) s[nt][i] = 0.f;
        #pragma unroll
        for (int ks = 0; ks < 4; ++ks) {
            uint32_t kbyte = (uint32_t)ks * 32;
            uint32_t ah[4], al[4], bh[4][4], bl[4][4];
            uint32_t ad = sb + ((qRow + kbyte + aK) ^ qXor);
            ldsm4(ah, ad);
            ldsm4(al, ad + 16384);
            #pragma unroll
            for (int np = 0; np < 4; ++np) {
                uint32_t bd = kb + ((kRow[np] + kbyte + bK) ^ kXor[np]);
                ldsm4(bh[np], bd);
                ldsm4(bl[np], bd + 8192);
            }
            #pragma unroll
            for (int np = 0; np < 4; ++np)
                #pragma unroll
                for (int hf = 0; hf < 2; ++hf) {
                    float* cc = s[np * 2 + hf];
                    mma16816(cc, ah, &bh[np][hf * 2]);
                    mma16816(cc, ah, &bl[np][hf * 2]);
                    mma16816(cc, al, &bh[np][hf * 2]);
                }
        }

        // online softmax in exp2 domain (logits pre-scaled via QSCALE in q)
        #pragma unroll
        for (int i = 0; i < 2; ++i) {
            float mx = -1e30f;
            #pragma unroll
            for (int nt = 0; nt < 8; ++nt)
                mx = fmaxf(mx, fmaxf(s[nt][2*i], s[nt][2*i+1]));
            mx = fmaxf(mx, __shfl_xor_sync(0xffffffffu, mx, 1));
            mx = fmaxf(mx, __shfl_xor_sync(0xffffffffu, mx, 2));
            float mnew = fmaxf(mreg[i], mx);
            float corr = ex2f(mreg[i] - mnew);
            mreg[i] = mnew;
            float rs = 0.f;
            #pragma unroll
            for (int nt = 0; nt < 8; ++nt) {
                float p0 = ex2f(s[nt][2*i]   - mnew);
                float p1 = ex2f(s[nt][2*i+1] - mnew);
                s[nt][2*i] = p0; s[nt][2*i+1] = p1;
                rs += p0 + p1;
            }
            rs += __shfl_xor_sync(0xffffffffu, rs, 1);
            rs += __shfl_xor_sync(0xffffffffu, rs, 2);
            lreg[i] = lreg[i] * corr + rs;
            #pragma unroll
            for (int nt = 0; nt < 8; ++nt) {
                accO[nt][2*i]   *= corr;
                accO[nt][2*i+1] *= corr;
            }
        }

        // O += P V (3-term split); pack P per kp to limit liveness
        #pragma unroll
        for (int kp = 0; kp < 4; ++kp) {
            uint32_t paH[4], paL[4];
            #pragma unroll
            for (int q4 = 0; q4 < 4; ++q4) {
                int nt = kp * 2 + (q4 >> 1);
                int e0 = (q4 & 1) * 2;
                split2(s[nt][e0], s[nt][e0 + 1], paH[q4], paL[q4]);
            }
            uint32_t vrow = (uint32_t)(kp * 16 + keyB) * 128;
            uint32_t vbh[4][4], vbl[4][4];
            #pragma unroll
            for (int np = 0; np < 4; ++np) {
                uint32_t bd = vb + ((vrow + (uint32_t)(np * 16 + dhB) * 2) ^ vXor);
                ldsm4t(vbh[np], bd);
                ldsm4t(vbl[np], bd + 8192);
            }
            #pragma unroll
            for (int np = 0; np < 4; ++np)
                #pragma unroll
                for (int hf = 0; hf < 2; ++hf) {
                    float* cc = accO[np * 2 + hf];
                    mma16816(cc, paH, &vbh[np][hf * 2]);
                    mma16816(cc, paH, &vbl[np][hf * 2]);
                    mma16816(cc, paL, &vbh[np][hf * 2]);
                }
        }
        __syncthreads();   // seal all reads of this stage before next iteration overwrites it
    }

    // epilogue: hi/lo bf16 att only
    #pragma unroll
    for (int i = 0; i < 2; ++i) {
        float inv = 1.0f / lreg[i];
        int row = t0 + w * 16 + (lane >> 2) + i * 8;
        size_t rb = base + (size_t)row * DIMK;
        #pragma unroll
        for (int nt = 0; nt < 8; ++nt) {
            int col = nt * 8 + (lane & 3) * 2;
            float f0 = accO[nt][2*i] * inv, f1 = accO[nt][2*i+1] * inv;
            uint32_t hp, lp;
            split2(f0, f1, hp, lp);
            *(uint32_t*)(g_att_h + rb + col) = hp;
            *(uint32_t*)(g_att_l + rb + col) = lp;
        }
    }
}

// ---------------- launch ----------------
extern "C" void kernel_launch(void* const* d_in, const int* in_sizes, int n_in,
                              void* d_out, int out_size)
{
    (void)in_sizes; (void)n_in; (void)out_size;
    const float* x      = (const float*)d_in[0];
    const float* m_tok  = (const float*)d_in[1];
    const float* norm_g = (const float*)d_in[2];
    const float* norm_b = (const float*)d_in[3];
    const float* mnorm_g= (const float*)d_in[4];
    const float* mnorm_b= (const float*)d_in[5];
    const float* Wq = (const float*)d_in[6];
    const float* Aq = (const float*)d_in[7];
    const float* Bq = (const float*)d_in[8];
    const float* Gq = (const float*)d_in[9];
    const float* Wk = (const float*)d_in[10];
    const float* Ak = (const float*)d_in[11];
    const float* Bk = (const float*)d_in[12];
    const float* Gk = (const float*)d_in[13];
    const float* Wv = (const float*)d_in[14];
    const float* Av = (const float*)d_in[15];
    const float* Bv = (const float*)d_in[16];
    const float* Gv = (const float*)d_in[17];
    const float* Wo = (const float*)d_in[18];
    const float* Ao = (const float*)d_in[19];
    const float* Bo = (const float*)d_in[20];
    const float* Go = (const float*)d_in[21];
    float* out = (float*)d_out;

    __nv_bfloat16 *p_xnh, *p_xnl, *p_mnh, *p_mnl;
    cudaGetSymbolAddress((void**)&p_xnh, g_xn_h);
    cudaGetSymbolAddress((void**)&p_xnl, g_xn_l);
    cudaGetSymbolAddress((void**)&p_mnh, g_mn_h);
    cudaGetSymbolAddress((void**)&p_mnl, g_mn_l);

    const int GSMEM = 2 * 65536 + 4 * 6144;        // 152 KB
    const int ASMEM = 32768 + 2 * 32768;           // 96 KB
    const int RSMEM = 2 * 40960;                   // 80 KB
    cudaFuncSetAttribute(gemm_qkv_kernel, cudaFuncAttributeMaxDynamicSharedMemorySize, GSMEM);
    cudaFuncSetAttribute(gemm_o_kernel,   cudaFuncAttributeMaxDynamicSharedMemorySize, GSMEM);
    cudaFuncSetAttribute(attn_mma_kernel, cudaFuncAttributeMaxDynamicSharedMemorySize, ASMEM);
    cudaFuncSetAttribute(lr_xm_kernel,    cudaFuncAttributeMaxDynamicSharedMemorySize, RSMEM);
    cudaFuncSetAttribute(lr_o_kernel,     cudaFuncAttributeMaxDynamicSharedMemorySize, RSMEM);

    cvt_w4_kernel<<<dim3(1024, 4), 256>>>(Wq, Wk, Wv, Wo);
    cvt_bv_kernel<<<112, 256>>>(Bq, Bk, Bv, Bo, Aq, Ak, Av, Gq, Gk, Gv, Go, Ao);

    ln2_kernel<<<dim3(NTOK, 2), 256>>>(x, norm_g, norm_b, p_xnh, p_xnl,
                                       m_tok, mnorm_g, mnorm_b, p_mnh, p_mnl);

    lr_xm_kernel<<<dim3(32, 2), 256, RSMEM>>>();
    combine_qkv_kernel<<<256, 256>>>();

    gemm_qkv_kernel<<<dim3(8, 32, 3), 256, GSMEM>>>();

    attn_mma_kernel<<<dim3(16, 16, 2), 256, ASMEM>>>();

    lr_o_kernel<<<32, 256, RSMEM>>>();
    gemm_o_kernel<<<dim3(8, 32), 256, GSMEM>>>(out);
}

// round 17
// speedup vs baseline: 1.0662x; 1.0191x over previous
#include <cuda_runtime.h>
#include <cuda_bf16.h>
#include <math.h>
#include <stdint.h>

#define NTOK 4096            // B*T
#define DIMK 1024
#define NHEAD 16
#define DHEAD 64

// 0.125 * log2(e): folded into q so softmax is exp2(s - m)
#define QSCALE 0.18033688011112042f

// ---------------- scratch (device globals; no allocs allowed) ----------------
__device__ float g_go  [NTOK * 8];
__device__ float g_resx[NTOK * 32];
__device__ float g_resm[NTOK * 32];

__device__ __nv_bfloat16 g_xn_h [NTOK * DIMK];
__device__ __nv_bfloat16 g_xn_l [NTOK * DIMK];
__device__ __nv_bfloat16 g_mn_h [NTOK * DIMK];
__device__ __nv_bfloat16 g_mn_l [NTOK * DIMK];
__device__ __nv_bfloat16 g_q_h  [NTOK * DIMK];
__device__ __nv_bfloat16 g_q_l  [NTOK * DIMK];
__device__ __nv_bfloat16 g_k_h  [NTOK * DIMK];
__device__ __nv_bfloat16 g_k_l  [NTOK * DIMK];
__device__ __nv_bfloat16 g_v_h  [NTOK * DIMK];
__device__ __nv_bfloat16 g_v_l  [NTOK * DIMK];
__device__ __nv_bfloat16 g_att_h[NTOK * DIMK];
__device__ __nv_bfloat16 g_att_l[NTOK * DIMK];
__device__ __nv_bfloat16 g_w_h  [4 * DIMK * DIMK];
__device__ __nv_bfloat16 g_w_l  [4 * DIMK * DIMK];
__device__ __nv_bfloat16 g_b16_h[4 * DIMK * 16];
__device__ __nv_bfloat16 g_b16_l[4 * DIMK * 16];
__device__ __nv_bfloat16 g_ax_h [32 * DIMK];
__device__ __nv_bfloat16 g_ax_l [32 * DIMK];
__device__ __nv_bfloat16 g_gm_h [32 * DIMK];
__device__ __nv_bfloat16 g_gm_l [32 * DIMK];
__device__ __nv_bfloat16 g_ao_h [32 * DIMK];
__device__ __nv_bfloat16 g_ao_l [32 * DIMK];
__device__ __nv_bfloat16 g_lq_h [NTOK * 16];
__device__ __nv_bfloat16 g_lq_l [NTOK * 16];
__device__ __nv_bfloat16 g_lk_h [NTOK * 16];
__device__ __nv_bfloat16 g_lk_l [NTOK * 16];
__device__ __nv_bfloat16 g_lv_h [NTOK * 16];
__device__ __nv_bfloat16 g_lv_l [NTOK * 16];
__device__ __nv_bfloat16 g_lo_h [NTOK * 16];
__device__ __nv_bfloat16 g_lo_l [NTOK * 16];

// ---------------- helpers ----------------
__device__ __forceinline__ uint32_t smem_u32(const void* p) {
    uint32_t a;
    asm("{ .reg .u64 t; cvta.to.shared.u64 t, %1; cvt.u32.u64 %0, t; }" : "=r"(a) : "l"(p));
    return a;
}

__device__ __forceinline__ void cpa16(uint32_t s, const void* g) {
    asm volatile("cp.async.cg.shared.global [%0], [%1], 16;" :: "r"(s), "l"(g));
}
#define CP_COMMIT() asm volatile("cp.async.commit_group;" ::: "memory")
#define CP_WAIT1()  asm volatile("cp.async.wait_group 1;" ::: "memory")
#define CP_WAIT0()  asm volatile("cp.async.wait_group 0;" ::: "memory")

__device__ __forceinline__ void ldsm4(uint32_t* r, uint32_t addr) {
    asm volatile("ldmatrix.sync.aligned.m8n8.x4.shared.b16 {%0,%1,%2,%3}, [%4];"
        : "=r"(r[0]), "=r"(r[1]), "=r"(r[2]), "=r"(r[3]) : "r"(addr));
}
__device__ __forceinline__ void ldsm4t(uint32_t* r, uint32_t addr) {
    asm volatile("ldmatrix.sync.aligned.m8n8.x4.trans.shared.b16 {%0,%1,%2,%3}, [%4];"
        : "=r"(r[0]), "=r"(r[1]), "=r"(r[2]), "=r"(r[3]) : "r"(addr));
}

__device__ __forceinline__ void mma16816(float* c, const uint32_t* a, const uint32_t* b) {
    asm volatile(
        "mma.sync.aligned.m16n8k16.row.col.f32.bf16.bf16.f32 "
        "{%0,%1,%2,%3}, {%4,%5,%6,%7}, {%8,%9}, {%0,%1,%2,%3};"
        : "+f"(c[0]), "+f"(c[1]), "+f"(c[2]), "+f"(c[3])
        : "r"(a[0]), "r"(a[1]), "r"(a[2]), "r"(a[3]), "r"(b[0]), "r"(b[1]));
}

__device__ __forceinline__ uint32_t swz128u(uint32_t o) { return o ^ ((o >> 3) & 0x70); }

__device__ __forceinline__ void splitf(float x, __nv_bfloat16& h, __nv_bfloat16& l) {
    h = __float2bfloat16(x);
    l = __float2bfloat16(x - __bfloat162float(h));
}
__device__ __forceinline__ uint32_t packbf(float f0, float f1) {
    uint32_t r;
    asm("cvt.rn.bf16x2.f32 %0, %1, %2;" : "=r"(r) : "f"(f1), "f"(f0));
    return r;
}
__device__ __forceinline__ void split2(float f0, float f1, uint32_t& hp, uint32_t& lp) {
    hp = packbf(f0, f1);
    float h0 = __uint_as_float(hp << 16);
    float h1 = __uint_as_float(hp & 0xffff0000u);
    lp = packbf(f0 - h0, f1 - h1);
}
__device__ __forceinline__ float ex2f(float x) {
    float r;
    asm("ex2.approx.f32 %0, %1;" : "=f"(r) : "f"(x));
    return r;
}

// ---------------- LayerNorm (x and m_tok in one launch; hi/lo bf16 outputs only) ----------------
__global__ void ln2_kernel(const float* __restrict__ in0, const float* __restrict__ g0,
                           const float* __restrict__ b0,
                           __nv_bfloat16* __restrict__ hi0, __nv_bfloat16* __restrict__ lo0,
                           const float* __restrict__ in1, const float* __restrict__ g1,
                           const float* __restrict__ b1,
                           __nv_bfloat16* __restrict__ hi1, __nv_bfloat16* __restrict__ lo1)
{
    int which = blockIdx.y;
    const float* in = which ? in1 : in0;
    const float* g  = which ? g1  : g0;
    const float* b  = which ? b1  : b0;
    __nv_bfloat16* hi = which ? hi1 : hi0;
    __nv_bfloat16* lo = which ? lo1 : lo0;
    int row = blockIdx.x;
    int tid = threadIdx.x;
    float4 a = ((const float4*)(in + (size_t)row * DIMK))[tid];
    float s = a.x + a.y + a.z + a.w;
    float q = a.x*a.x + a.y*a.y + a.z*a.z + a.w*a.w;
    #pragma unroll
    for (int o = 16; o; o >>= 1) {
        s += __shfl_xor_sync(0xffffffffu, s, o);
        q += __shfl_xor_sync(0xffffffffu, q, o);
    }
    __shared__ float ss[8], sq[8];
    __shared__ float s_mean, s_rstd;
    int warp = tid >> 5, lane = tid & 31;
    if (lane == 0) { ss[warp] = s; sq[warp] = q; }
    __syncthreads();
    if (tid == 0) {
        float ts = 0.f, tq = 0.f;
        #pragma unroll
        for (int i = 0; i < 8; i++) { ts += ss[i]; tq += sq[i]; }
        float mean = ts * (1.0f / DIMK);
        float var  = tq * (1.0f / DIMK) - mean * mean;
        s_mean = mean;
        s_rstd = rsqrtf(var + 1e-5f);
    }
    __syncthreads();
    float mean = s_mean, rstd = s_rstd;
    float4 gg = ((const float4*)g)[tid];
    float4 bb = ((const float4*)b)[tid];
    float4 r;
    r.x = (a.x - mean) * rstd * gg.x + bb.x;
    r.y = (a.y - mean) * rstd * gg.y + bb.y;
    r.z = (a.z - mean) * rstd * gg.z + bb.z;
    r.w = (a.w - mean) * rstd * gg.w + bb.w;
    uint32_t h0, l0, h1, l1;
    split2(r.x, r.y, h0, l0);
    split2(r.z, r.w, h1, l1);
    ((uint32_t*)(hi + (size_t)row * DIMK))[tid*2]   = h0;
    ((uint32_t*)(hi + (size_t)row * DIMK))[tid*2+1] = h1;
    ((uint32_t*)(lo + (size_t)row * DIMK))[tid*2]   = l0;
    ((uint32_t*)(lo + (size_t)row * DIMK))[tid*2+1] = l1;
}

// ---------------- fp32 -> hi/lo bf16 weight conversion (all 4 slots, one launch) ----------------
__global__ void cvt_w4_kernel(const float* __restrict__ w0, const float* __restrict__ w1,
                              const float* __restrict__ w2, const float* __restrict__ w3)
{
    int slot = blockIdx.y;
    const float* in = (slot == 0) ? w0 : (slot == 1) ? w1 : (slot == 2) ? w2 : w3;
    size_t i = (size_t)blockIdx.x * blockDim.x + threadIdx.x;
    float4 v = ((const float4*)in)[i];
    uint32_t hA, lA, hB, lB;
    split2(v.x, v.y, hA, lA);
    split2(v.z, v.w, hB, lB);
    size_t o = (size_t)slot * DIMK * DIMK + i * 4;
    *(uint32_t*)(g_w_h + o)     = hA;
    *(uint32_t*)(g_w_h + o + 2) = hB;
    *(uint32_t*)(g_w_l + o)     = lA;
    *(uint32_t*)(g_w_l + o + 2) = lB;
}

// ---------------- B pads + A/G/Ao vectors, one launch ----------------
__global__ void cvt_bv_kernel(const float* __restrict__ b0, const float* __restrict__ b1,
                              const float* __restrict__ b2, const float* __restrict__ b3,
                              const float* __restrict__ Aq, const float* __restrict__ Ak,
                              const float* __restrict__ Av, const float* __restrict__ Gq,
                              const float* __restrict__ Gk, const float* __restrict__ Gv,
                              const float* __restrict__ Go, const float* __restrict__ Ao)
{
    int bx = blockIdx.x;
    int tid = threadIdx.x;
    if (bx < 16) {
        int slot = bx >> 2;
        const float* B = (slot == 0) ? b0 : (slot == 1) ? b1 : (slot == 2) ? b2 : b3;
        int r = (bx & 3) * 256 + tid;
        size_t o = (size_t)slot * DIMK * 16 + (size_t)r * 16;
        __nv_bfloat16 z = __float2bfloat16(0.f);
        #pragma unroll
        for (int j = 0; j < 8; j++) {
            __nv_bfloat16 h, l;
            splitf(B[r * 8 + j], h, l);
            g_b16_h[o + j] = h; g_b16_l[o + j] = l;
            g_b16_h[o + 8 + j] = z; g_b16_l[o + 8 + j] = z;
        }
    } else {
        int idx = bx - 16;
        int mat = idx >> 5;
        int r = idx & 31;
        const float* src = 0;
        __nv_bfloat16 *dh, *dl;
        if (mat == 0) {
            dh = g_ax_h; dl = g_ax_l;
            if (r < 8) src = Aq + r * DIMK;
            else if (r < 16) src = Ak + (r - 8) * DIMK;
            else if (r < 24) src = Av + (r - 16) * DIMK;
        } else if (mat == 1) {
            dh = g_gm_h; dl = g_gm_l;
            if (r < 8) src = Gq + r * DIMK;
            else if (r < 16) src = Gk + (r - 8) * DIMK;
            else if (r < 24) src = Gv + (r - 16) * DIMK;
            else src = Go + (r - 24) * DIMK;
        } else {
            dh = g_ao_h; dl = g_ao_l;
            if (r < 8) src = Ao + r * DIMK;
        }
        float4 v = src ? ((const float4*)src)[tid] : make_float4(0.f, 0.f, 0.f, 0.f);
        uint32_t hA, lA, hB, lB;
        split2(v.x, v.y, hA, lA);
        split2(v.z, v.w, hB, lB);
        size_t o = (size_t)r * DIMK + (size_t)tid * 4;
        *(uint32_t*)(dh + o)     = hA;
        *(uint32_t*)(dh + o + 2) = hB;
        *(uint32_t*)(dl + o)     = lA;
        *(uint32_t*)(dl + o + 2) = lB;
    }
}

// ---------------- thin split-bf16 GEMM core (128 threads, M-tile 64) ----------------
// acc[4][4] += X64[.,1024] . V[32,1024]^T
// Stage s at s*24576: Xh+0 (8KB), Xl+8192, Vh+16384 (4KB), Vl+20480.
#define LRSTAGE 24576
__device__ __forceinline__
void lr_accum(char* smem,
              const __nv_bfloat16* __restrict__ Xh, const __nv_bfloat16* __restrict__ Xl,
              const __nv_bfloat16* __restrict__ Vh, const __nv_bfloat16* __restrict__ Vl,
              int bm, float acc[4][4])
{
    const uint32_t sb = smem_u32(smem);
    const int tid = threadIdx.x;          // 128
    const int lane = tid & 31, w = tid >> 5;   // w in 0..3

    const int ar = tid >> 1, asg = (tid & 1) * 4;        // 64 rows, 2 thr/row
    const int br = (tid & 63) >> 1, bsg = (tid & 1) * 4; // 32 rows, 2 thr/row
    auto load_stage = [&](int c, int s) {
        uint32_t sbase = sb + (uint32_t)s * LRSTAGE;
        size_t offx = (size_t)(bm + ar) * DIMK + c * 64;
        #pragma unroll
        for (int j = 0; j < 4; ++j) {
            int seg = asg + j;
            uint32_t so = sbase + swz128u((uint32_t)ar * 128 + seg * 16);
            cpa16(so,        Xh + offx + seg * 8);
            cpa16(so + 8192, Xl + offx + seg * 8);
        }
        if (tid < 64) {
            size_t offv = (size_t)br * DIMK + c * 64;
            #pragma unroll
            for (int j = 0; j < 4; ++j) {
                int seg = bsg + j;
                uint32_t so = sbase + 16384 + swz128u((uint32_t)br * 128 + seg * 16);
                cpa16(so,        Vh + offv + seg * 8);
                cpa16(so + 4096, Vl + offv + seg * 8);
            }
        }
    };

    const int rA = w * 16 + (lane & 15);
    const uint32_t aRow = (uint32_t)rA * 128;
    const uint32_t aXor = (uint32_t)((rA & 7) << 4);
    const uint32_t aK = (uint32_t)((lane >> 4) << 4);
    uint32_t bRow[2], bXor[2];
    #pragma unroll
    for (int np = 0; np < 2; ++np) {
        int rB = np * 16 + ((lane >> 4) & 1) * 8 + (lane & 7);
        bRow[np] = (uint32_t)rB * 128;
        bXor[np] = (uint32_t)((rB & 7) << 4);
    }
    const uint32_t bK = (uint32_t)(((lane >> 3) & 1) * 16);

    load_stage(0, 0); CP_COMMIT();
    #pragma unroll 1
    for (int c = 0; c < 16; ++c) {
        CP_WAIT0();
        __syncthreads();
        if (c + 1 < 16) { load_stage(c + 1, (c + 1) & 1); CP_COMMIT(); }
        uint32_t sbase = sb + (uint32_t)(c & 1) * LRSTAGE;
        #pragma unroll
        for (int ks = 0; ks < 4; ++ks) {
            uint32_t kb = (uint32_t)ks * 32;
            uint32_t ah[4], al[4];
            uint32_t ad = sbase + ((aRow + kb + aK) ^ aXor);
            ldsm4(ah, ad);
            ldsm4(al, ad + 8192);
            #pragma unroll
            for (int np = 0; np < 2; ++np) {
                uint32_t bh[4], bl[4];
                uint32_t bd = sbase + 16384 + ((bRow[np] + kb + bK) ^ bXor[np]);
                ldsm4(bh, bd);
                ldsm4(bl, bd + 4096);
                #pragma unroll
                for (int hf = 0; hf < 2; ++hf) {
                    float* cc = acc[np * 2 + hf];
                    mma16816(cc, ah, &bh[hf * 2]);
                    mma16816(cc, ah, &bl[hf * 2]);
                    mma16816(cc, al, &bh[hf * 2]);
                }
            }
        }
        __syncthreads();
    }
}

// x/m low-rank projections -> g_resx / g_resm   (grid (64, 2), 128 thr)
__global__ __launch_bounds__(128, 4)
void lr_xm_kernel()
{
    extern __shared__ char smem[];
    const int tid = threadIdx.x;
    const int lane = tid & 31, w = tid >> 5;
    const int bm = blockIdx.x * 64;
    float acc[4][4];
    #pragma unroll
    for (int nt = 0; nt < 4; ++nt)
        #pragma unroll
        for (int i = 0; i < 4; ++i) acc[nt][i] = 0.f;
    float* out;
    if (blockIdx.y == 0) { lr_accum(smem, g_xn_h, g_xn_l, g_ax_h, g_ax_l, bm, acc); out = g_resx; }
    else                 { lr_accum(smem, g_mn_h, g_mn_l, g_gm_h, g_gm_l, bm, acc); out = g_resm; }
    int m0 = bm + w * 16 + (lane >> 2);
    #pragma unroll
    for (int nt = 0; nt < 4; ++nt) {
        int n0 = nt * 8 + (lane & 3) * 2;
        *(float2*)(out + (size_t)m0 * 32 + n0)       = make_float2(acc[nt][0], acc[nt][1]);
        *(float2*)(out + (size_t)(m0 + 8) * 32 + n0) = make_float2(acc[nt][2], acc[nt][3]);
    }
}

// o low-rank projection with FUSED combine: lo = 0.25 * (att.Ao^T) * go   (grid 64, 128 thr)
__global__ __launch_bounds__(128, 4)
void lr_o_kernel()
{
    extern __shared__ char smem[];
    const int tid = threadIdx.x;
    const int lane = tid & 31, w = tid >> 5;
    const int bm = blockIdx.x * 64;
    float acc[4][4];
    #pragma unroll
    for (int nt = 0; nt < 4; ++nt)
        #pragma unroll
        for (int i = 0; i < 4; ++i) acc[nt][i] = 0.f;
    lr_accum(smem, g_att_h, g_att_l, g_ao_h, g_ao_l, bm, acc);

    #pragma unroll
    for (int i = 0; i < 2; ++i) {
        int m = bm + w * 16 + (lane >> 2) + i * 8;
        #pragma unroll
        for (int nt = 0; nt < 4; ++nt) {
            int n0 = nt * 8 + (lane & 3) * 2;
            if (n0 < 8) {
                float2 go = *(const float2*)(g_go + (size_t)m * 8 + n0);
                uint32_t hp, lp;
                split2(0.25f * acc[nt][2*i] * go.x, 0.25f * acc[nt][2*i+1] * go.y, hp, lp);
                *(uint32_t*)(g_lo_h + (size_t)m * 16 + n0) = hp;
                *(uint32_t*)(g_lo_l + (size_t)m * 16 + n0) = lp;
                *(uint32_t*)(g_lo_h + (size_t)m * 16 + n0 + 8) = 0u;
                *(uint32_t*)(g_lo_l + (size_t)m * 16 + n0 + 8) = 0u;
            }
        }
    }
}

// ---------------- combine: low-rank activations + gates (qkv path) ----------------
__global__ void combine_qkv_kernel()
{
    int idx = blockIdx.x * blockDim.x + threadIdx.x;
    int t = idx >> 4, j = idx & 15;
    float vq = 0.f, vk = 0.f, vv = 0.f;
    if (j < 8) {
        const float* rx = g_resx + (size_t)t * 32;
        const float* rm = g_resm + (size_t)t * 32;
        vq = 0.25f * rx[j]      * rm[j];
        vk = 0.25f * rx[8 + j]  * rm[8 + j];
        vv = 0.25f * rx[16 + j] * rm[16 + j];
        g_go[t * 8 + j] = rm[24 + j];
    }
    __nv_bfloat16 h, l;
    splitf(vq, h, l); g_lq_h[t*16 + j] = h; g_lq_l[t*16 + j] = l;
    splitf(vk, h, l); g_lk_h[t*16 + j] = h; g_lk_l[t*16 + j] = l;
    splitf(vv, h, l); g_lv_h[t*16 + j] = h; g_lv_l[t*16 + j] = l;
}

// ---------------- HMMA split-bf16 GEMM body + folded rank-8 LoRA (champion config) ----------------
__device__ __forceinline__
void gemm_body(char* smem,
               const __nv_bfloat16* __restrict__ Xh, const __nv_bfloat16* __restrict__ Xl,
               const __nv_bfloat16* __restrict__ Wh, const __nv_bfloat16* __restrict__ Wl,
               const __nv_bfloat16* __restrict__ Lh, const __nv_bfloat16* __restrict__ Ll,
               const __nv_bfloat16* __restrict__ Bh, const __nv_bfloat16* __restrict__ Bl,
               float* __restrict__ C,
               __nv_bfloat16* __restrict__ Ch, __nv_bfloat16* __restrict__ Cl,
               float cscale)
{
    const uint32_t sb = smem_u32(smem);
    const int tid = threadIdx.x;
    const int lane = tid & 31, w = tid >> 5;
    const int wm = (w & 3) * 32, wn = (w >> 2) * 64;
    const int bm = blockIdx.y * 128, bn = blockIdx.x * 128;

    // LoRA tiles -> smem
    {
        int row = tid >> 1, cs = tid & 1;
        uint32_t so = 131072u + (uint32_t)row * 48 + cs * 16;
        size_t gl = (size_t)(bm + row) * 16 + cs * 8;
        size_t gb = (size_t)(bn + row) * 16 + cs * 8;
        *(int4*)(smem + so)          = *(const int4*)(Lh + gl);
        *(int4*)(smem + so + 6144)   = *(const int4*)(Ll + gl);
        *(int4*)(smem + so + 12288)  = *(const int4*)(Bh + gb);
        *(int4*)(smem + so + 18432)  = *(const int4*)(Bl + gb);
    }

    const int r0 = tid >> 3, seg = tid & 7;
    auto load_stage = [&](int c, int s) {
        uint32_t sbase = sb + (uint32_t)s * 65536;
        #pragma unroll
        for (int j = 0; j < 4; ++j) {
            int row = r0 + j * 32;
            size_t offx = (size_t)(bm + row) * DIMK + c * 64 + seg * 8;
            size_t offw = (size_t)(bn + row) * DIMK + c * 64 + seg * 8;
            uint32_t so = sbase + swz128u((uint32_t)row * 128 + seg * 16);
            cpa16(so,          Xh + offx);
            cpa16(so + 16384,  Xl + offx);
            cpa16(so + 32768,  Wh + offw);
            cpa16(so + 49152,  Wl + offw);
        }
    };

    uint32_t aRow[2], aXor[2];
    #pragma unroll
    for (int mt = 0; mt < 2; ++mt) {
        int rA = wm + mt * 16 + (lane & 15);
        aRow[mt] = (uint32_t)rA * 128;
        aXor[mt] = (uint32_t)((rA & 7) << 4);
    }
    const uint32_t aK = (uint32_t)((lane >> 4) << 4);
    uint32_t bRow[4], bXor[4];
    #pragma unroll
    for (int np = 0; np < 4; ++np) {
        int rB = wn + np * 16 + ((lane >> 4) & 1) * 8 + (lane & 7);
        bRow[np] = (uint32_t)rB * 128;
        bXor[np] = (uint32_t)((rB & 7) << 4);
    }
    const uint32_t bK = (uint32_t)(((lane >> 3) & 1) * 16);

    float acc[2][8][4];
    #pragma unroll
    for (int mt = 0; mt < 2; ++mt)
        #pragma unroll
        for (int nt = 0; nt < 8; ++nt)
            #pragma unroll
            for (int i = 0; i < 4; ++i) acc[mt][nt][i] = 0.f;

    auto compute = [&](int s) {
        uint32_t sbase = sb + (uint32_t)s * 65536;
        #pragma unroll
        for (int ks = 0; ks < 4; ++ks) {
            uint32_t kb = (uint32_t)ks * 32;
            uint32_t ah[2][4], al[2][4], bh[4][4], bl[4][4];
            #pragma unroll
            for (int mt = 0; mt < 2; ++mt) {
                uint32_t ad = sbase + ((aRow[mt] + kb + aK) ^ aXor[mt]);
                ldsm4(ah[mt], ad);
                ldsm4(al[mt], ad + 16384);
            }
            #pragma unroll
            for (int np = 0; np < 4; ++np) {
                uint32_t bd = sbase + 32768 + ((bRow[np] + kb + bK) ^ bXor[np]);
                ldsm4(bh[np], bd);
                ldsm4(bl[np], bd + 16384);
            }
            #pragma unroll
            for (int mt = 0; mt < 2; ++mt)
                #pragma unroll
                for (int np = 0; np < 4; ++np)
                    #pragma unroll
                    for (int hf = 0; hf < 2; ++hf) {
                        float* cc = acc[mt][np * 2 + hf];
                        mma16816(cc, ah[mt], &bh[np][hf * 2]);
                        mma16816(cc, ah[mt], &bl[np][hf * 2]);
                        mma16816(cc, al[mt], &bh[np][hf * 2]);
                    }
        }
    };

    load_stage(0, 0); CP_COMMIT();
    #pragma unroll 1
    for (int c = 0; c < 16; ++c) {
        if (c < 15) { load_stage(c + 1, (c + 1) & 1); CP_COMMIT(); CP_WAIT1(); }
        else        { CP_WAIT0(); }
        __syncthreads();
        compute(c & 1);
        __syncthreads();
    }

    // LoRA k16 step
    {
        uint32_t lb = sb + 131072u;
        uint32_t ah[2][4], al[2][4], bh[4][4], bl[4][4];
        #pragma unroll
        for (int mt = 0; mt < 2; ++mt) {
            uint32_t rA = (uint32_t)(wm + mt * 16 + (lane & 15));
            uint32_t ad = lb + rA * 48 + aK;
            ldsm4(ah[mt], ad);
            ldsm4(al[mt], ad + 6144);
        }
        #pragma unroll
        for (int np = 0; np < 4; ++np) {
            uint32_t rB = (uint32_t)(wn + np * 16 + ((lane >> 4) & 1) * 8 + (lane & 7));
            uint32_t bd = lb + 12288 + rB * 48 + bK;
            ldsm4(bh[np], bd);
            ldsm4(bl[np], bd + 6144);
        }
        #pragma unroll
        for (int mt = 0; mt < 2; ++mt)
            #pragma unroll
            for (int np = 0; np < 4; ++np)
                #pragma unroll
                for (int hf = 0; hf < 2; ++hf) {
                    float* cc = acc[mt][np * 2 + hf];
                    mma16816(cc, ah[mt], &bh[np][hf * 2]);
                    mma16816(cc, ah[mt], &bl[np][hf * 2]);
                    mma16816(cc, al[mt], &bh[np][hf * 2]);
                }
    }

    // epilogue (cscale folded into bf16 outputs; fp32 path unscaled)
    #pragma unroll
    for (int mt = 0; mt < 2; ++mt) {
        int m0 = bm + wm + mt * 16 + (lane >> 2);
        #pragma unroll
        for (int nt = 0; nt < 8; ++nt) {
            int n0 = bn + wn + nt * 8 + (lane & 3) * 2;
            float* a = acc[mt][nt];
            if (C) {
                *(float2*)(C + (size_t)m0 * DIMK + n0)       = make_float2(a[0], a[1]);
                *(float2*)(C + (size_t)(m0 + 8) * DIMK + n0) = make_float2(a[2], a[3]);
            }
            if (Ch) {
                uint32_t hp0, lp0, hp1, lp1;
                split2(a[0] * cscale, a[1] * cscale, hp0, lp0);
                split2(a[2] * cscale, a[3] * cscale, hp1, lp1);
                *(uint32_t*)(Ch + (size_t)m0 * DIMK + n0)       = hp0;
                *(uint32_t*)(Ch + (size_t)(m0 + 8) * DIMK + n0) = hp1;
                *(uint32_t*)(Cl + (size_t)m0 * DIMK + n0)       = lp0;
                *(uint32_t*)(Cl + (size_t)(m0 + 8) * DIMK + n0) = lp1;
            }
        }
    }
}

__global__ __launch_bounds__(256, 1)
void gemm_qkv_kernel()
{
    extern __shared__ char smem[];
    int z = blockIdx.z;
    const __nv_bfloat16 *Lh, *Ll;
    __nv_bfloat16 *Ch, *Cl;
    float cs;
    if (z == 0)      { Lh = g_lq_h; Ll = g_lq_l; Ch = g_q_h; Cl = g_q_l; cs = QSCALE; }
    else if (z == 1) { Lh = g_lk_h; Ll = g_lk_l; Ch = g_k_h; Cl = g_k_l; cs = 1.f; }
    else             { Lh = g_lv_h; Ll = g_lv_l; Ch = g_v_h; Cl = g_v_l; cs = 1.f; }
    gemm_body(smem, g_xn_h, g_xn_l,
              g_w_h + (size_t)z * DIMK * DIMK, g_w_l + (size_t)z * DIMK * DIMK,
              Lh, Ll, g_b16_h + (size_t)z * DIMK * 16, g_b16_l + (size_t)z * DIMK * 16,
              (float*)0, Ch, Cl, cs);
}

__global__ __launch_bounds__(256, 1)
void gemm_o_kernel(float* __restrict__ out)
{
    extern __shared__ char smem[];
    gemm_body(smem, g_att_h, g_att_l,
              g_w_h + (size_t)3 * DIMK * DIMK, g_w_l + (size_t)3 * DIMK * DIMK,
              g_lo_h, g_lo_l, g_b16_h + (size_t)3 * DIMK * 16, g_b16_l + (size_t)3 * DIMK * 16,
              out, (__nv_bfloat16*)0, (__nv_bfloat16*)0, 1.f);
}

// ---------------- HMMA split-bf16 flash attention, block-causal (frame=256) ----------------
// WAIT1 deep prefetch, 1 CTA/SM, race-free via trailing __syncthreads().
__global__ __launch_bounds__(256, 1)
void attn_mma_kernel()
{
    extern __shared__ char smem[];
    const uint32_t sb = smem_u32(smem);
    int qt = 15 - (int)blockIdx.x;           // big frames first
    int h  = blockIdx.y;
    int b  = blockIdx.z;
    int t0 = qt << 7;
    int ntile = ((qt >> 1) + 1) << 2;        // key tiles of 64
    int tid = threadIdx.x, lane = tid & 31, w = tid >> 5;
    size_t base = ((size_t)b * 2048) * DIMK + h * DHEAD;

    // Q load (hi+lo): 128 rows x 128B each, 2 threads/row
    {
        int lrow = tid >> 1;
        int lsegb = (tid & 1) * 4;
        size_t g = base + (size_t)(t0 + lrow) * DIMK;
        #pragma unroll
        for (int j = 0; j < 4; ++j) {
            int seg = lsegb + j;
            uint32_t so = sb + swz128u((uint32_t)lrow * 128 + seg * 16);
            cpa16(so,         g_q_h + g + seg * 8);
            cpa16(so + 16384, g_q_l + g + seg * 8);
        }
    }
    auto load_kv = [&](int kt, int st) {
        uint32_t sv = sb + 32768 + (uint32_t)st * 32768;
        int lrow = tid >> 2;
        int lsegb = (tid & 3) * 2;
        size_t g = base + (size_t)((kt << 6) + lrow) * DIMK;
        #pragma unroll
        for (int j = 0; j < 2; ++j) {
            int seg = lsegb + j;
            uint32_t so = sv + swz128u((uint32_t)lrow * 128 + seg * 16);
            cpa16(so,         g_k_h + g + seg * 8);
            cpa16(so + 8192,  g_k_l + g + seg * 8);
            cpa16(so + 16384, g_v_h + g + seg * 8);
            cpa16(so + 24576, g_v_l + g + seg * 8);
        }
    };

    const int rA = w * 16 + (lane & 15);
    const uint32_t qRow = (uint32_t)rA * 128;
    const uint32_t qXor = (uint32_t)((rA & 7) << 4);
    const uint32_t aK = (uint32_t)((lane >> 4) << 4);
    uint32_t kRow[4], kXor[4];
    #pragma unroll
    for (int np = 0; np < 4; ++np) {
        int rB = np * 16 + ((lane >> 4) & 1) * 8 + (lane & 7);
        kRow[np] = (uint32_t)rB * 128;
        kXor[np] = (uint32_t)((rB & 7) << 4);
    }
    const uint32_t bK = (uint32_t)(((lane >> 3) & 1) * 16);
    const int keyB = ((lane >> 3) & 1) * 8 + (lane & 7);
    const int dhB  = ((lane >> 4) & 1) * 8;
    const uint32_t vXor = (uint32_t)((lane & 7) << 4);

    float accO[8][4];
    #pragma unroll
    for (int nt = 0; nt < 8; ++nt)
        #pragma unroll
        for (int i = 0; i < 4; ++i) accO[nt][i] = 0.f;
    float mreg[2] = {-1e30f, -1e30f};
    float lreg[2] = {0.f, 0.f};

    load_kv(0, 0); CP_COMMIT();

    #pragma unroll 1
    for (int kt = 0; kt < ntile; ++kt) {
        if (kt + 1 < ntile) { load_kv(kt + 1, (kt + 1) & 1); CP_COMMIT(); CP_WAIT1(); }
        else                { CP_WAIT0(); }
        __syncthreads();
        uint32_t kb = sb + 32768 + (uint32_t)(kt & 1) * 32768;
        uint32_t vb = kb + 16384;

        // S = QK^T (3-term split)
        float s[8][4];
        #pragma unroll
        for (int nt = 0; nt < 8; ++nt)
            #pragma unroll
            for (int i = 0; i < 4; ++i) s[nt][i] = 0.f;
        #pragma unroll
        for (int ks = 0; ks < 4; ++ks) {
            uint32_t kbyte = (uint32_t)ks * 32;
            uint32_t ah[4], al[4], bh[4][4], bl[4][4];
            uint32_t ad = sb + ((qRow + kbyte + aK) ^ qXor);
            ldsm4(ah, ad);
            ldsm4(al, ad + 16384);
            #pragma unroll
            for (int np = 0; np < 4; ++np) {
                uint32_t bd = kb + ((kRow[np] + kbyte + bK) ^ kXor[np]);
                ldsm4(bh[np], bd);
                ldsm4(bl[np], bd + 8192);
            }
            #pragma unroll
            for (int np = 0; np < 4; ++np)
                #pragma unroll
                for (int hf = 0; hf < 2; ++hf) {
                    float* cc = s[np * 2 + hf];
                    mma16816(cc, ah, &bh[np][hf * 2]);
                    mma16816(cc, ah, &bl[np][hf * 2]);
                    mma16816(cc, al, &bh[np][hf * 2]);
                }
        }

        // online softmax in exp2 domain (logits pre-scaled via QSCALE in q)
        #pragma unroll
        for (int i = 0; i < 2; ++i) {
            float mx = -1e30f;
            #pragma unroll
            for (int nt = 0; nt < 8; ++nt)
                mx = fmaxf(mx, fmaxf(s[nt][2*i], s[nt][2*i+1]));
            mx = fmaxf(mx, __shfl_xor_sync(0xffffffffu, mx, 1));
            mx = fmaxf(mx, __shfl_xor_sync(0xffffffffu, mx, 2));
            float mnew = fmaxf(mreg[i], mx);
            float corr = ex2f(mreg[i] - mnew);
            mreg[i] = mnew;
            float rs = 0.f;
            #pragma unroll
            for (int nt = 0; nt < 8; ++nt) {
                float p0 = ex2f(s[nt][2*i]   - mnew);
                float p1 = ex2f(s[nt][2*i+1] - mnew);
                s[nt][2*i] = p0; s[nt][2*i+1] = p1;
                rs += p0 + p1;
            }
            rs += __shfl_xor_sync(0xffffffffu, rs, 1);
            rs += __shfl_xor_sync(0xffffffffu, rs, 2);
            lreg[i] = lreg[i] * corr + rs;
            #pragma unroll
            for (int nt = 0; nt < 8; ++nt) {
                accO[nt][2*i]   *= corr;
                accO[nt][2*i+1] *= corr;
            }
        }

        // O += P V (3-term split); pack P per kp to limit liveness
        #pragma unroll
        for (int kp = 0; kp < 4; ++kp) {
            uint32_t paH[4], paL[4];
            #pragma unroll
            for (int q4 = 0; q4 < 4; ++q4) {
                int nt = kp * 2 + (q4 >> 1);
                int e0 = (q4 & 1) * 2;
                split2(s[nt][e0], s[nt][e0 + 1], paH[q4], paL[q4]);
            }
            uint32_t vrow = (uint32_t)(kp * 16 + keyB) * 128;
            uint32_t vbh[4][4], vbl[4][4];
            #pragma unroll
            for (int np = 0; np < 4; ++np) {
                uint32_t bd = vb + ((vrow + (uint32_t)(np * 16 + dhB) * 2) ^ vXor);
                ldsm4t(vbh[np], bd);
                ldsm4t(vbl[np], bd + 8192);
            }
            #pragma unroll
            for (int np = 0; np < 4; ++np)
                #pragma unroll
                for (int hf = 0; hf < 2; ++hf) {
                    float* cc = accO[np * 2 + hf];
                    mma16816(cc, paH, &vbh[np][hf * 2]);
                    mma16816(cc, paH, &vbl[np][hf * 2]);
                    mma16816(cc, paL, &vbh[np][hf * 2]);
                }
        }
        __syncthreads();   // seal all reads of this stage before next iteration overwrites it
    }

    // epilogue: hi/lo bf16 att only
    #pragma unroll
    for (int i = 0; i < 2; ++i) {
        float inv = 1.0f / lreg[i];
        int row = t0 + w * 16 + (lane >> 2) + i * 8;
        size_t rb = base + (size_t)row * DIMK;
        #pragma unroll
        for (int nt = 0; nt < 8; ++nt) {
            int col = nt * 8 + (lane & 3) * 2;
            float f0 = accO[nt][2*i] * inv, f1 = accO[nt][2*i+1] * inv;
            uint32_t hp, lp;
            split2(f0, f1, hp, lp);
            *(uint32_t*)(g_att_h + rb + col) = hp;
            *(uint32_t*)(g_att_l + rb + col) = lp;
        }
    }
}

// ---------------- launch ----------------
extern "C" void kernel_launch(void* const* d_in, const int* in_sizes, int n_in,
                              void* d_out, int out_size)
{
    (void)in_sizes; (void)n_in; (void)out_size;
    const float* x      = (const float*)d_in[0];
    const float* m_tok  = (const float*)d_in[1];
    const float* norm_g = (const float*)d_in[2];
    const float* norm_b = (const float*)d_in[3];
    const float* mnorm_g= (const float*)d_in[4];
    const float* mnorm_b= (const float*)d_in[5];
    const float* Wq = (const float*)d_in[6];
    const float* Aq = (const float*)d_in[7];
    const float* Bq = (const float*)d_in[8];
    const float* Gq = (const float*)d_in[9];
    const float* Wk = (const float*)d_in[10];
    const float* Ak = (const float*)d_in[11];
    const float* Bk = (const float*)d_in[12];
    const float* Gk = (const float*)d_in[13];
    const float* Wv = (const float*)d_in[14];
    const float* Av = (const float*)d_in[15];
    const float* Bv = (const float*)d_in[16];
    const float* Gv = (const float*)d_in[17];
    const float* Wo = (const float*)d_in[18];
    const float* Ao = (const float*)d_in[19];
    const float* Bo = (const float*)d_in[20];
    const float* Go = (const float*)d_in[21];
    float* out = (float*)d_out;

    __nv_bfloat16 *p_xnh, *p_xnl, *p_mnh, *p_mnl;
    cudaGetSymbolAddress((void**)&p_xnh, g_xn_h);
    cudaGetSymbolAddress((void**)&p_xnl, g_xn_l);
    cudaGetSymbolAddress((void**)&p_mnh, g_mn_h);
    cudaGetSymbolAddress((void**)&p_mnl, g_mn_l);

    const int GSMEM = 2 * 65536 + 4 * 6144;        // 152 KB
    const int ASMEM = 32768 + 2 * 32768;           // 96 KB
    const int RSMEM = 2 * LRSTAGE;                 // 48 KB
    cudaFuncSetAttribute(gemm_qkv_kernel, cudaFuncAttributeMaxDynamicSharedMemorySize, GSMEM);
    cudaFuncSetAttribute(gemm_o_kernel,   cudaFuncAttributeMaxDynamicSharedMemorySize, GSMEM);
    cudaFuncSetAttribute(attn_mma_kernel, cudaFuncAttributeMaxDynamicSharedMemorySize, ASMEM);
    cudaFuncSetAttribute(lr_xm_kernel,    cudaFuncAttributeMaxDynamicSharedMemorySize, RSMEM);
    cudaFuncSetAttribute(lr_o_kernel,     cudaFuncAttributeMaxDynamicSharedMemorySize, RSMEM);

    cvt_w4_kernel<<<dim3(1024, 4), 256>>>(Wq, Wk, Wv, Wo);
    cvt_bv_kernel<<<112, 256>>>(Bq, Bk, Bv, Bo, Aq, Ak, Av, Gq, Gk, Gv, Go, Ao);

    ln2_kernel<<<dim3(NTOK, 2), 256>>>(x, norm_g, norm_b, p_xnh, p_xnl,
                                       m_tok, mnorm_g, mnorm_b, p_mnh, p_mnl);

    lr_xm_kernel<<<dim3(64, 2), 128, RSMEM>>>();
    combine_qkv_kernel<<<256, 256>>>();

    gemm_qkv_kernel<<<dim3(8, 32, 3), 256, GSMEM>>>();

    attn_mma_kernel<<<dim3(16, 16, 2), 256, ASMEM>>>();

    lr_o_kernel<<<64, 128, RSMEM>>>();
    gemm_o_kernel<<<dim3(8, 32), 256, GSMEM>>>(out);
}